// round 12
// baseline (speedup 1.0000x reference)
#include <cuda_runtime.h>
#include <cuda_fp16.h>
#include <cstdint>

#define NS     25
#define NQ     200
#define NITEM  (NS + NQ)        // 225
#define FF     80
#define DD     512
#define WAY    5
#define BLK    128
#define NBLK   10               // packed upper-tri 128x128 blocks of 4x4 grid
#define BLKSZ  (BLK * BLK)      // 16384 halves per block
#define KPACK  (NBLK * BLKSZ)   // 163840
#define PITCH  136              // smem pitch (halves) for X slices
#define SLICE  (FF * PITCH)     // halves per slice buffer
#define NUNIT  (NBLK * NITEM)   // 2250
#define GGRID  296              // persistent CTAs (2/SM)

// -------- scratch (__device__ globals; no allocations allowed) --------------
__device__ __half g_Sn[NS * FF * DD];        // 2 MB   normalized supports
__device__ __half g_Qn[NQ * FF * DD];        // 16.4MB normalized queries
__device__ __half g_Gs[NS][KPACK];           // per-support Grams, frag order (x2 offdiag)
__device__ __half g_Gp[WAY][KPACK];          // class-summed Grams, frag order
__device__ __half g_Hp[NQ][KPACK];           // query Grams, frag order
__device__ float  g_bar[NITEM][DD];          // per-item feature-row sums
__device__ float  g_sbarsum[WAY][DD];
__device__ int    g_cls_cnt[WAY];
__device__ float  g_S2[WAY][NQ];

__constant__ int c_bi[NBLK] = {0,0,0,0,1,1,1,2,2,3};
__constant__ int c_bj[NBLK] = {0,1,2,3,1,2,3,2,3,3};

// ---------------------------------------------------------------------------
// K1 (fused): per-item normalize + rowsum. One CTA per item. (proven)
// ---------------------------------------------------------------------------
__global__ void __launch_bounds__(256) norm_kernel(
    const float* __restrict__ sg, const float* __restrict__ sl,
    const float* __restrict__ qg, const float* __restrict__ ql)
{
    __shared__ float snorm[FF];
    const int item = blockIdx.x;
    const int tid  = threadIdx.x;
    const int lane = tid & 31;
    const int warp = tid >> 5;

    const float* gbase;
    const float* lbase;
    __half* dst;
    if (item < NS) {
        gbase = sg + (size_t)item * 16 * DD;
        lbase = sl + (size_t)item * 64 * DD;
        dst   = g_Sn + (size_t)item * FF * DD;
    } else {
        int q = item - NS;
        gbase = qg + (size_t)q * 16 * DD;
        lbase = ql + (size_t)q * 64 * DD;
        dst   = g_Qn + (size_t)q * FF * DD;
    }

    for (int f = warp; f < FF; f += 8) {
        const float4* src = (const float4*)((f < 16) ? gbase + (size_t)f * DD
                                                     : lbase + (size_t)(f - 16) * DD);
        float ss = 0.f;
#pragma unroll
        for (int i = 0; i < 4; i++) {
            float4 v = src[lane + 32 * i];
            ss += v.x * v.x + v.y * v.y + v.z * v.z + v.w * v.w;
        }
#pragma unroll
        for (int o = 16; o; o >>= 1) ss += __shfl_xor_sync(0xFFFFFFFFu, ss, o);
        if (lane == 0) snorm[f] = rsqrtf(fmaxf(ss, 1e-24f));
    }
    __syncthreads();

    float sx = 0.f, sy = 0.f;
#pragma unroll 4
    for (int f = 0; f < FF; f++) {
        const float2* src = (const float2*)((f < 16) ? gbase + (size_t)f * DD
                                                     : lbase + (size_t)(f - 16) * DD);
        float2 v = src[tid];
        float rn = snorm[f];
        float a = v.x * rn, b = v.y * rn;
        sx += a; sy += b;
        *(__half2*)(dst + (size_t)f * DD + 2 * tid) = __floats2half2_rn(a, b);
    }
    g_bar[item][2 * tid + 0] = sx;
    g_bar[item][2 * tid + 1] = sy;
}

// ---------------------------------------------------------------------------
// K2: class counts, class-summed row-sums, zero S2 (proven)
// ---------------------------------------------------------------------------
__global__ void prep_kernel(const long long* __restrict__ labels)
{
    __shared__ int cnt[WAY];
    __shared__ int sup[WAY][NS];
    int t = threadIdx.x;  // 512
    if (t == 0) {
        for (int c = 0; c < WAY; c++) cnt[c] = 0;
        for (int s = 0; s < NS; s++) {
            int c = (int)labels[s];
            sup[c][cnt[c]++] = s;
        }
        for (int c = 0; c < WAY; c++) g_cls_cnt[c] = cnt[c];
    }
    __syncthreads();
    if (t < DD) {
#pragma unroll
        for (int c = 0; c < WAY; c++) {
            float a = 0.f;
            for (int i = 0; i < cnt[c]; i++) a += g_bar[sup[c][i]][t];
            g_sbarsum[c][t] = a;
        }
    }
    for (int i = t; i < WAY * NQ; i += blockDim.x)
        (&g_S2[0][0])[i] = 0.f;
}

// ---------------------------------------------------------------------------
// shared mma machinery
// ---------------------------------------------------------------------------
__device__ __forceinline__ void ldsm_x4_t(uint32_t (&r)[4], const __half* p)
{
    uint32_t a = (uint32_t)__cvta_generic_to_shared(p);
    asm volatile("ldmatrix.sync.aligned.m8n8.x4.trans.shared.b16 {%0,%1,%2,%3}, [%4];"
                 : "=r"(r[0]), "=r"(r[1]), "=r"(r[2]), "=r"(r[3]) : "r"(a));
}

__device__ __forceinline__ void mma16816(float (&d)[4], const uint32_t (&a)[4],
                                         uint32_t b0, uint32_t b1)
{
    asm volatile("mma.sync.aligned.m16n8k16.row.col.f32.f16.f16.f32 "
                 "{%0,%1,%2,%3},{%4,%5,%6,%7},{%8,%9},{%0,%1,%2,%3};"
                 : "+f"(d[0]), "+f"(d[1]), "+f"(d[2]), "+f"(d[3])
                 : "r"(a[0]), "r"(a[1]), "r"(a[2]), "r"(a[3]), "r"(b0), "r"(b1));
}

__device__ __forceinline__ void gram_block_mma(
    const __half* sX0, const __half* pB, float (&acc)[2][8][4],
    int m_base, int n_base, int lane)
{
    const int a_krow = ((lane >> 4) << 3) + (lane & 7);
    const int a_coff = ((lane >> 3) & 1) << 3;
    const int b_krow = (((lane >> 3) & 1) << 3) + (lane & 7);
    const int b_coff = (lane >> 4) << 3;

#pragma unroll
    for (int k16 = 0; k16 < FF / 16; k16++) {
        const int k0 = k16 * 16;
        uint32_t a[2][4];
#pragma unroll
        for (int mt = 0; mt < 2; mt++)
            ldsm_x4_t(a[mt], &sX0[(k0 + a_krow) * PITCH + m_base + mt * 16 + a_coff]);
#pragma unroll
        for (int nt = 0; nt < 4; nt++) {
            uint32_t bf[4];
            ldsm_x4_t(bf, &pB[(k0 + b_krow) * PITCH + n_base + nt * 16 + b_coff]);
#pragma unroll
            for (int mt = 0; mt < 2; mt++) {
                mma16816(acc[mt][2 * nt + 0], a[mt], bf[0], bf[1]);
                mma16816(acc[mt][2 * nt + 1], a[mt], bf[2], bf[3]);
            }
        }
    }
}

// ---------------------------------------------------------------------------
// K3: persistent pipelined Gram kernel (R7 exact form, proven).
// ---------------------------------------------------------------------------
extern __shared__ char dynsmem[];

__device__ __forceinline__ void issue_unit_load(int u, int stage, int tid)
{
    const int item = u / NBLK, b = u % NBLK;
    const int bi = c_bi[b], bj = c_bj[b];
    const __half* base = (item < NS) ? g_Sn + (size_t)item * FF * DD
                                     : g_Qn + (size_t)(item - NS) * FF * DD;
    __half* s0 = (__half*)dynsmem + stage * 2 * SLICE;
    const int nch = (bi == bj) ? 1280 : 2560;
    for (int ch = tid; ch < nch; ch += 256) {
        int tile = (ch >= 1280) ? 1 : 0;
        int rem  = ch - tile * 1280;
        int r = rem >> 4, cc = rem & 15;
        int colblk = tile ? bj : bi;
        const __half* src = base + (size_t)r * DD + colblk * 128 + cc * 8;
        __half* dsts = s0 + tile * SLICE + r * PITCH + cc * 8;
        uint32_t dst = (uint32_t)__cvta_generic_to_shared(dsts);
        asm volatile("cp.async.cg.shared.global [%0], [%1], 16;" :: "r"(dst), "l"(src));
    }
    asm volatile("cp.async.commit_group;");
}

__global__ void __launch_bounds__(256, 2) gram_kernel()
{
    const int tid  = threadIdx.x;
    const int lane = tid & 31;
    const int warp = tid >> 5;
    const int m_base = (warp >> 1) * 32;
    const int n_base = (warp & 1) * 64;

    int u = blockIdx.x;
    if (u >= NUNIT) return;

    issue_unit_load(u, 0, tid);
    int stage = 0;

    for (; u < NUNIT; u += gridDim.x) {
        const int nextu = u + gridDim.x;
        if (nextu < NUNIT) {
            issue_unit_load(nextu, stage ^ 1, tid);
            asm volatile("cp.async.wait_group 1;");
        } else {
            asm volatile("cp.async.wait_group 0;");
        }
        __syncthreads();

        const int item = u / NBLK, b = u % NBLK;
        const bool diag = (c_bi[b] == c_bj[b]);
        const __half* s0 = (const __half*)dynsmem + stage * 2 * SLICE;
        const __half* pB = diag ? s0 : s0 + SLICE;

        float acc[2][8][4];
#pragma unroll
        for (int mt = 0; mt < 2; mt++)
#pragma unroll
            for (int nt = 0; nt < 8; nt++)
#pragma unroll
                for (int i = 0; i < 4; i++) acc[mt][nt][i] = 0.f;

        gram_block_mma(s0, pB, acc, m_base, n_base, lane);

        const float scale = (item < NS && !diag) ? 2.f : 1.f;
        __half* out = ((item < NS) ? g_Gs[item] : g_Hp[item - NS]) + (size_t)b * BLKSZ;
#pragma unroll
        for (int j = 0; j < 8; j++) {
            const int mt = j >> 2, nt0 = (j & 3) * 2;
            __half2 h[4];
            h[0] = __floats2half2_rn(acc[mt][nt0][0] * scale, acc[mt][nt0][1] * scale);
            h[1] = __floats2half2_rn(acc[mt][nt0][2] * scale, acc[mt][nt0][3] * scale);
            h[2] = __floats2half2_rn(acc[mt][nt0 + 1][0] * scale, acc[mt][nt0 + 1][1] * scale);
            h[3] = __floats2half2_rn(acc[mt][nt0 + 1][2] * scale, acc[mt][nt0 + 1][3] * scale);
            *(int4*)(out + (size_t)(j * 256 + tid) * 8) = *(int4*)h;
        }
        __syncthreads();
        stage ^= 1;
    }
}

// ---------------------------------------------------------------------------
// K4: classsum v3 — int2 granularity, 160 CTAs (2x warps), indicator weights.
// ---------------------------------------------------------------------------
__global__ void __launch_bounds__(256) classsum_kernel(const long long* __restrict__ labels)
{
    __shared__ float ind[NS][WAY];
    const int tid = threadIdx.x;
    if (tid < NS * WAY) {
        int s = tid / WAY, c = tid % WAY;
        ind[s][c] = ((int)labels[s] == c) ? 1.f : 0.f;
    }
    __syncthreads();

    const int base = blockIdx.x * 1024 + tid * 4;   // 4 halves per thread

    float acc[WAY][4];
#pragma unroll
    for (int c = 0; c < WAY; c++)
#pragma unroll
        for (int j = 0; j < 4; j++) acc[c][j] = 0.f;

#pragma unroll 5
    for (int s = 0; s < NS; s++) {
        uint2 v = *(const uint2*)&g_Gs[s][base];
        float2 p0 = __half22float2(*(const __half2*)&v.x);
        float2 p1 = __half22float2(*(const __half2*)&v.y);
        float f[4] = {p0.x, p0.y, p1.x, p1.y};
#pragma unroll
        for (int c = 0; c < WAY; c++) {
            const float w = ind[s][c];
#pragma unroll
            for (int j = 0; j < 4; j++) acc[c][j] += f[j] * w;
        }
    }

#pragma unroll
    for (int c = 0; c < WAY; c++) {
        uint2 o;
        *(__half2*)&o.x = __floats2half2_rn(acc[c][0], acc[c][1]);
        *(__half2*)&o.y = __floats2half2_rn(acc[c][2], acc[c][3]);
        *(uint2*)&g_Gp[c][base] = o;
    }
}

// ---------------------------------------------------------------------------
// K5: dot v6 — G chunk staged in smem (40KB), regs ~70, 3 CTAs/SM.
// grid (40 kchunks x 25 query-octets).
// ---------------------------------------------------------------------------
__global__ void __launch_bounds__(256) dot_kernel()
{
    __shared__ __half sG[WAY * 4096];               // 40 KB
    __shared__ float red[8][8][WAY];

    const int kc   = blockIdx.x;            // 0..39
    const int q0   = blockIdx.y * 8;        // 0..192
    const int tid  = threadIdx.x;
    const int lane = tid & 31;
    const int warp = tid >> 5;

    // stage G: 2560 int4, coalesced from L2-resident g_Gp
    for (int i = tid; i < WAY * 512; i += 256) {
        int c = i >> 9, off = (i & 511) * 8;
        *(int4*)&sG[c * 4096 + off] = *(const int4*)&g_Gp[c][kc * 4096 + off];
    }
    __syncthreads();

    const int kb = warp * 512 + lane * 8;

    float acc[8][WAY];
#pragma unroll
    for (int qi = 0; qi < 8; qi++)
#pragma unroll
        for (int c = 0; c < WAY; c++) acc[qi][c] = 0.f;

#pragma unroll
    for (int qi = 0; qi < 8; qi++) {
        const __half* Hq = g_Hp[q0 + qi] + kc * 4096 + kb;
        __half2 H[8];
        *(int4*)&H[0] = *(const int4*)(Hq);
        *(int4*)&H[4] = *(const int4*)(Hq + 256);
#pragma unroll
        for (int c = 0; c < WAY; c++) {
            __half2 G[8];
            *(int4*)&G[0] = *(const int4*)&sG[c * 4096 + kb];
            *(int4*)&G[4] = *(const int4*)&sG[c * 4096 + kb + 256];
            __half2 a = __hmul2(G[0], H[0]);
#pragma unroll
            for (int j = 1; j < 8; j++) a = __hfma2(G[j], H[j], a);
            float2 f = __half22float2(a);
            acc[qi][c] = f.x + f.y;
        }
    }

#pragma unroll
    for (int o = 16; o; o >>= 1)
#pragma unroll
        for (int qi = 0; qi < 8; qi++)
#pragma unroll
            for (int c = 0; c < WAY; c++)
                acc[qi][c] += __shfl_xor_sync(0xFFFFFFFFu, acc[qi][c], o);

    if (lane == 0)
#pragma unroll
        for (int qi = 0; qi < 8; qi++)
#pragma unroll
            for (int c = 0; c < WAY; c++) red[warp][qi][c] = acc[qi][c];
    __syncthreads();

    if (tid < 8 * WAY) {
        int qi = tid / WAY, c = tid % WAY;
        float s = 0.f;
#pragma unroll
        for (int w = 0; w < 8; w++) s += red[w][qi][c];
        atomicAdd(&g_S2[c][q0 + qi], s);
    }
}

// ---------------------------------------------------------------------------
// K6: logits (proven fast form)
// ---------------------------------------------------------------------------
__global__ void logits_kernel(float* __restrict__ out)
{
    int warp = (blockIdx.x * blockDim.x + threadIdx.x) >> 5;
    int lane = threadIdx.x & 31;
    if (warp >= NQ) return;
    const int q = warp;

    float s1[WAY] = {0.f, 0.f, 0.f, 0.f, 0.f};
    const float* qb = g_bar[NS + q];
    for (int k = lane; k < DD; k += 32) {
        float qv = qb[k];
#pragma unroll
        for (int c = 0; c < WAY; c++) s1[c] += g_sbarsum[c][k] * qv;
    }
#pragma unroll
    for (int o = 16; o; o >>= 1)
#pragma unroll
        for (int c = 0; c < WAY; c++)
            s1[c] += __shfl_xor_sync(0xFFFFFFFFu, s1[c], o);

    if (lane < WAY) {
        int c = lane;
        float cnt = (float)g_cls_cnt[c];
        out[q * WAY + c] = -2.f * (float)(FF * FF) + (4.f * s1[c] - 2.f * g_S2[c][q]) / cnt;
    }
}

// ---------------------------------------------------------------------------
extern "C" void kernel_launch(void* const* d_in, const int* in_sizes, int n_in,
                              void* d_out, int out_size)
{
    const float*     sg  = (const float*)d_in[0];
    const float*     sl  = (const float*)d_in[1];
    const long long* lab = (const long long*)d_in[2];
    const float*     qg  = (const float*)d_in[3];
    const float*     ql  = (const float*)d_in[4];
    float*           out = (float*)d_out;

    const int smem = 2 * 2 * SLICE * 2;   // 2 stages x 2 slices = 87040 B
    static bool attr_set = false;
    if (!attr_set) {
        cudaFuncSetAttribute(gram_kernel, cudaFuncAttributeMaxDynamicSharedMemorySize, smem);
        attr_set = true;
    }

    norm_kernel<<<NITEM, 256>>>(sg, sl, qg, ql);       // normalize + rowsum
    prep_kernel<<<1, 512>>>(lab);
    gram_kernel<<<GGRID, 256, smem>>>();               // persistent, 2250 units
    classsum_kernel<<<KPACK / 1024, 256>>>(lab);       // 160 CTAs
    dot_kernel<<<dim3(40, 25), 256>>>();               // 1000 CTAs, smem G
    logits_kernel<<<(NQ * 32 + 255) / 256, 256>>>(out);
}

// round 13
// speedup vs baseline: 1.0463x; 1.0463x over previous
#include <cuda_runtime.h>
#include <cuda_fp16.h>
#include <cstdint>

#define NS     25
#define NQ     200
#define NITEM  (NS + NQ)        // 225
#define FF     80
#define DD     512
#define WAY    5
#define BLK    128
#define NBLK   10               // packed upper-tri 128x128 blocks of 4x4 grid
#define BLKSZ  (BLK * BLK)      // 16384 halves per block
#define KPACK  (NBLK * BLKSZ)   // 163840
#define PITCH  136              // smem pitch (halves) for X slices
#define SLICE  (FF * PITCH)     // halves per slice buffer
#define NUNIT  (NBLK * NITEM)   // 2250
#define GGRID  296              // persistent CTAs (2/SM)

// -------- scratch (__device__ globals; no allocations allowed) --------------
__device__ __half g_Sn[NS * FF * DD];        // 2 MB   normalized supports
__device__ __half g_Qn[NQ * FF * DD];        // 16.4MB normalized queries
__device__ __half g_Gs[NS][KPACK];           // per-support Grams, frag order (x2 offdiag)
__device__ __half g_Gp[WAY][KPACK];          // class-summed Grams, frag order
__device__ __half g_Hp[NQ][KPACK];           // query Grams, frag order
__device__ float  g_bar[NITEM][DD];          // per-item feature-row sums
__device__ float  g_sbarsum[WAY][DD];
__device__ int    g_cls_cnt[WAY];
__device__ int    g_cls_sup[WAY][NS];
__device__ float  g_S2[WAY][NQ];

__constant__ int c_bi[NBLK] = {0,0,0,0,1,1,1,2,2,3};
__constant__ int c_bj[NBLK] = {0,1,2,3,1,2,3,2,3,3};

// ---------------------------------------------------------------------------
// K1 (fused): per-item normalize + rowsum. One CTA per item. (proven)
// ---------------------------------------------------------------------------
__global__ void __launch_bounds__(256) norm_kernel(
    const float* __restrict__ sg, const float* __restrict__ sl,
    const float* __restrict__ qg, const float* __restrict__ ql)
{
    __shared__ float snorm[FF];
    const int item = blockIdx.x;
    const int tid  = threadIdx.x;
    const int lane = tid & 31;
    const int warp = tid >> 5;

    const float* gbase;
    const float* lbase;
    __half* dst;
    if (item < NS) {
        gbase = sg + (size_t)item * 16 * DD;
        lbase = sl + (size_t)item * 64 * DD;
        dst   = g_Sn + (size_t)item * FF * DD;
    } else {
        int q = item - NS;
        gbase = qg + (size_t)q * 16 * DD;
        lbase = ql + (size_t)q * 64 * DD;
        dst   = g_Qn + (size_t)q * FF * DD;
    }

    for (int f = warp; f < FF; f += 8) {
        const float4* src = (const float4*)((f < 16) ? gbase + (size_t)f * DD
                                                     : lbase + (size_t)(f - 16) * DD);
        float ss = 0.f;
#pragma unroll
        for (int i = 0; i < 4; i++) {
            float4 v = src[lane + 32 * i];
            ss += v.x * v.x + v.y * v.y + v.z * v.z + v.w * v.w;
        }
#pragma unroll
        for (int o = 16; o; o >>= 1) ss += __shfl_xor_sync(0xFFFFFFFFu, ss, o);
        if (lane == 0) snorm[f] = rsqrtf(fmaxf(ss, 1e-24f));
    }
    __syncthreads();

    float sx = 0.f, sy = 0.f;
#pragma unroll 4
    for (int f = 0; f < FF; f++) {
        const float2* src = (const float2*)((f < 16) ? gbase + (size_t)f * DD
                                                     : lbase + (size_t)(f - 16) * DD);
        float2 v = src[tid];
        float rn = snorm[f];
        float a = v.x * rn, b = v.y * rn;
        sx += a; sy += b;
        *(__half2*)(dst + (size_t)f * DD + 2 * tid) = __floats2half2_rn(a, b);
    }
    g_bar[item][2 * tid + 0] = sx;
    g_bar[item][2 * tid + 1] = sy;
}

// ---------------------------------------------------------------------------
// K2: class lists/counts, class-summed row-sums, zero S2 (proven)
// ---------------------------------------------------------------------------
__global__ void prep_kernel(const long long* __restrict__ labels)
{
    __shared__ int cnt[WAY];
    __shared__ int sup[WAY][NS];
    int t = threadIdx.x;  // 512
    if (t == 0) {
        for (int c = 0; c < WAY; c++) cnt[c] = 0;
        for (int s = 0; s < NS; s++) {
            int c = (int)labels[s];
            sup[c][cnt[c]++] = s;
        }
        for (int c = 0; c < WAY; c++) {
            g_cls_cnt[c] = cnt[c];
            for (int i = 0; i < cnt[c]; i++) g_cls_sup[c][i] = sup[c][i];
        }
    }
    __syncthreads();
    if (t < DD) {
#pragma unroll
        for (int c = 0; c < WAY; c++) {
            float a = 0.f;
            for (int i = 0; i < cnt[c]; i++) a += g_bar[sup[c][i]][t];
            g_sbarsum[c][t] = a;
        }
    }
    for (int i = t; i < WAY * NQ; i += blockDim.x)
        (&g_S2[0][0])[i] = 0.f;
}

// ---------------------------------------------------------------------------
// shared mma machinery
// ---------------------------------------------------------------------------
__device__ __forceinline__ void ldsm_x4_t(uint32_t (&r)[4], const __half* p)
{
    uint32_t a = (uint32_t)__cvta_generic_to_shared(p);
    asm volatile("ldmatrix.sync.aligned.m8n8.x4.trans.shared.b16 {%0,%1,%2,%3}, [%4];"
                 : "=r"(r[0]), "=r"(r[1]), "=r"(r[2]), "=r"(r[3]) : "r"(a));
}

__device__ __forceinline__ void mma16816(float (&d)[4], const uint32_t (&a)[4],
                                         uint32_t b0, uint32_t b1)
{
    asm volatile("mma.sync.aligned.m16n8k16.row.col.f32.f16.f16.f32 "
                 "{%0,%1,%2,%3},{%4,%5,%6,%7},{%8,%9},{%0,%1,%2,%3};"
                 : "+f"(d[0]), "+f"(d[1]), "+f"(d[2]), "+f"(d[3])
                 : "r"(a[0]), "r"(a[1]), "r"(a[2]), "r"(a[3]), "r"(b0), "r"(b1));
}

__device__ __forceinline__ void gram_block_mma(
    const __half* sX0, const __half* pB, float (&acc)[2][8][4],
    int m_base, int n_base, int lane)
{
    const int a_krow = ((lane >> 4) << 3) + (lane & 7);
    const int a_coff = ((lane >> 3) & 1) << 3;
    const int b_krow = (((lane >> 3) & 1) << 3) + (lane & 7);
    const int b_coff = (lane >> 4) << 3;

#pragma unroll
    for (int k16 = 0; k16 < FF / 16; k16++) {
        const int k0 = k16 * 16;
        uint32_t a[2][4];
#pragma unroll
        for (int mt = 0; mt < 2; mt++)
            ldsm_x4_t(a[mt], &sX0[(k0 + a_krow) * PITCH + m_base + mt * 16 + a_coff]);
#pragma unroll
        for (int nt = 0; nt < 4; nt++) {
            uint32_t bf[4];
            ldsm_x4_t(bf, &pB[(k0 + b_krow) * PITCH + n_base + nt * 16 + b_coff]);
#pragma unroll
            for (int mt = 0; mt < 2; mt++) {
                mma16816(acc[mt][2 * nt + 0], a[mt], bf[0], bf[1]);
                mma16816(acc[mt][2 * nt + 1], a[mt], bf[2], bf[3]);
            }
        }
    }
}

// ---------------------------------------------------------------------------
// K3: persistent pipelined Gram kernel (R7 exact form, proven 27.7us).
// ---------------------------------------------------------------------------
extern __shared__ char dynsmem[];

__device__ __forceinline__ void issue_unit_load(int u, int stage, int tid)
{
    const int item = u / NBLK, b = u % NBLK;
    const int bi = c_bi[b], bj = c_bj[b];
    const __half* base = (item < NS) ? g_Sn + (size_t)item * FF * DD
                                     : g_Qn + (size_t)(item - NS) * FF * DD;
    __half* s0 = (__half*)dynsmem + stage * 2 * SLICE;
    const int nch = (bi == bj) ? 1280 : 2560;
    for (int ch = tid; ch < nch; ch += 256) {
        int tile = (ch >= 1280) ? 1 : 0;
        int rem  = ch - tile * 1280;
        int r = rem >> 4, cc = rem & 15;
        int colblk = tile ? bj : bi;
        const __half* src = base + (size_t)r * DD + colblk * 128 + cc * 8;
        __half* dsts = s0 + tile * SLICE + r * PITCH + cc * 8;
        uint32_t dst = (uint32_t)__cvta_generic_to_shared(dsts);
        asm volatile("cp.async.cg.shared.global [%0], [%1], 16;" :: "r"(dst), "l"(src));
    }
    asm volatile("cp.async.commit_group;");
}

__global__ void __launch_bounds__(256, 2) gram_kernel()
{
    const int tid  = threadIdx.x;
    const int lane = tid & 31;
    const int warp = tid >> 5;
    const int m_base = (warp >> 1) * 32;
    const int n_base = (warp & 1) * 64;

    int u = blockIdx.x;
    if (u >= NUNIT) return;

    issue_unit_load(u, 0, tid);
    int stage = 0;

    for (; u < NUNIT; u += gridDim.x) {
        const int nextu = u + gridDim.x;
        if (nextu < NUNIT) {
            issue_unit_load(nextu, stage ^ 1, tid);
            asm volatile("cp.async.wait_group 1;");
        } else {
            asm volatile("cp.async.wait_group 0;");
        }
        __syncthreads();

        const int item = u / NBLK, b = u % NBLK;
        const bool diag = (c_bi[b] == c_bj[b]);
        const __half* s0 = (const __half*)dynsmem + stage * 2 * SLICE;
        const __half* pB = diag ? s0 : s0 + SLICE;

        float acc[2][8][4];
#pragma unroll
        for (int mt = 0; mt < 2; mt++)
#pragma unroll
            for (int nt = 0; nt < 8; nt++)
#pragma unroll
                for (int i = 0; i < 4; i++) acc[mt][nt][i] = 0.f;

        gram_block_mma(s0, pB, acc, m_base, n_base, lane);

        const float scale = (item < NS && !diag) ? 2.f : 1.f;
        __half* out = ((item < NS) ? g_Gs[item] : g_Hp[item - NS]) + (size_t)b * BLKSZ;
#pragma unroll
        for (int j = 0; j < 8; j++) {
            const int mt = j >> 2, nt0 = (j & 3) * 2;
            __half2 h[4];
            h[0] = __floats2half2_rn(acc[mt][nt0][0] * scale, acc[mt][nt0][1] * scale);
            h[1] = __floats2half2_rn(acc[mt][nt0][2] * scale, acc[mt][nt0][3] * scale);
            h[2] = __floats2half2_rn(acc[mt][nt0 + 1][0] * scale, acc[mt][nt0 + 1][1] * scale);
            h[3] = __floats2half2_rn(acc[mt][nt0 + 1][2] * scale, acc[mt][nt0 + 1][3] * scale);
            *(int4*)(out + (size_t)(j * 256 + tid) * 8) = *(int4*)h;
        }
        __syncthreads();
        stage ^= 1;
    }
}

// ---------------------------------------------------------------------------
// K4: classsum v5 — per-class CTAs: grid (160 kchunks x 5 classes) = 800 CTAs.
// Each CTA sums only its class's ~5 supports. Chain 25 -> 5, no indicators.
// ---------------------------------------------------------------------------
__global__ void __launch_bounds__(256) classsum_kernel()
{
    const int c    = blockIdx.y;
    const int base = blockIdx.x * 1024 + threadIdx.x * 4;   // 4 halves/thread
    const int cnt  = g_cls_cnt[c];

    float a0 = 0.f, a1 = 0.f, a2 = 0.f, a3 = 0.f;
#pragma unroll 5
    for (int i = 0; i < cnt; i++) {
        uint2 v = *(const uint2*)&g_Gs[g_cls_sup[c][i]][base];
        float2 p0 = __half22float2(*(const __half2*)&v.x);
        float2 p1 = __half22float2(*(const __half2*)&v.y);
        a0 += p0.x; a1 += p0.y; a2 += p1.x; a3 += p1.y;
    }
    uint2 o;
    *(__half2*)&o.x = __floats2half2_rn(a0, a1);
    *(__half2*)&o.y = __floats2half2_rn(a2, a3);
    *(uint2*)&g_Gp[c][base] = o;
}

// ---------------------------------------------------------------------------
// K5: dot v7 — kchunk 2048, grid (80 x 25) = 2000 CTAs, ~80 regs (3 CTAs/SM).
// G = 5 int4 in regs; 8 queries' H streamed coalesced (independent loads).
// ---------------------------------------------------------------------------
__global__ void __launch_bounds__(256) dot_kernel()
{
    const int kc   = blockIdx.x;            // 0..79
    const int q0   = blockIdx.y * 8;        // 0..192
    const int tid  = threadIdx.x;
    const int lane = tid & 31;
    const int warp = tid >> 5;
    const int kbase = kc * 2048 + tid * 8;  // 16B per lane, warp-contiguous

    __half2 G[WAY][4];
#pragma unroll
    for (int c = 0; c < WAY; c++)
        *(int4*)&G[c][0] = *(const int4*)&g_Gp[c][kbase];

    float acc[8][WAY];
#pragma unroll
    for (int qi = 0; qi < 8; qi++)
#pragma unroll
        for (int c = 0; c < WAY; c++) acc[qi][c] = 0.f;

    // 8 independent H loads (compiler can batch them for MLP)
    __half2 H[8][4];
#pragma unroll
    for (int qi = 0; qi < 8; qi++)
        *(int4*)&H[qi][0] = *(const int4*)(g_Hp[q0 + qi] + kbase);

#pragma unroll
    for (int qi = 0; qi < 8; qi++) {
#pragma unroll
        for (int c = 0; c < WAY; c++) {
            __half2 a = __hmul2(G[c][0], H[qi][0]);
            a = __hfma2(G[c][1], H[qi][1], a);
            a = __hfma2(G[c][2], H[qi][2], a);
            a = __hfma2(G[c][3], H[qi][3], a);
            float2 f = __half22float2(a);
            acc[qi][c] = f.x + f.y;
        }
    }

#pragma unroll
    for (int o = 16; o; o >>= 1)
#pragma unroll
        for (int qi = 0; qi < 8; qi++)
#pragma unroll
            for (int c = 0; c < WAY; c++)
                acc[qi][c] += __shfl_xor_sync(0xFFFFFFFFu, acc[qi][c], o);

    __shared__ float red[8][8][WAY];
    if (lane == 0)
#pragma unroll
        for (int qi = 0; qi < 8; qi++)
#pragma unroll
            for (int c = 0; c < WAY; c++) red[warp][qi][c] = acc[qi][c];
    __syncthreads();

    if (tid < 8 * WAY) {
        int qi = tid / WAY, c = tid % WAY;
        float s = 0.f;
#pragma unroll
        for (int w = 0; w < 8; w++) s += red[w][qi][c];
        atomicAdd(&g_S2[c][q0 + qi], s);
    }
}

// ---------------------------------------------------------------------------
// K6: logits (proven fast form)
// ---------------------------------------------------------------------------
__global__ void logits_kernel(float* __restrict__ out)
{
    int warp = (blockIdx.x * blockDim.x + threadIdx.x) >> 5;
    int lane = threadIdx.x & 31;
    if (warp >= NQ) return;
    const int q = warp;

    float s1[WAY] = {0.f, 0.f, 0.f, 0.f, 0.f};
    const float* qb = g_bar[NS + q];
    for (int k = lane; k < DD; k += 32) {
        float qv = qb[k];
#pragma unroll
        for (int c = 0; c < WAY; c++) s1[c] += g_sbarsum[c][k] * qv;
    }
#pragma unroll
    for (int o = 16; o; o >>= 1)
#pragma unroll
        for (int c = 0; c < WAY; c++)
            s1[c] += __shfl_xor_sync(0xFFFFFFFFu, s1[c], o);

    if (lane < WAY) {
        int c = lane;
        float cnt = (float)g_cls_cnt[c];
        out[q * WAY + c] = -2.f * (float)(FF * FF) + (4.f * s1[c] - 2.f * g_S2[c][q]) / cnt;
    }
}

// ---------------------------------------------------------------------------
extern "C" void kernel_launch(void* const* d_in, const int* in_sizes, int n_in,
                              void* d_out, int out_size)
{
    const float*     sg  = (const float*)d_in[0];
    const float*     sl  = (const float*)d_in[1];
    const long long* lab = (const long long*)d_in[2];
    const float*     qg  = (const float*)d_in[3];
    const float*     ql  = (const float*)d_in[4];
    float*           out = (float*)d_out;

    const int smem = 2 * 2 * SLICE * 2;   // 2 stages x 2 slices = 87040 B
    static bool attr_set = false;
    if (!attr_set) {
        cudaFuncSetAttribute(gram_kernel, cudaFuncAttributeMaxDynamicSharedMemorySize, smem);
        attr_set = true;
    }

    norm_kernel<<<NITEM, 256>>>(sg, sl, qg, ql);       // normalize + rowsum
    prep_kernel<<<1, 512>>>(lab);
    gram_kernel<<<GGRID, 256, smem>>>();               // persistent, 2250 units
    classsum_kernel<<<dim3(KPACK / 1024, WAY), 256>>>();  // 800 CTAs, per-class
    dot_kernel<<<dim3(80, 25), 256>>>();               // 2000 CTAs
    logits_kernel<<<(NQ * 32 + 255) / 256, 256>>>(out);
}

// round 14
// speedup vs baseline: 1.1904x; 1.1377x over previous
#include <cuda_runtime.h>
#include <cuda_fp16.h>
#include <cstdint>

#define NS     25
#define NQ     200
#define NITEM  (NS + NQ)        // 225
#define FF     80
#define DD     512
#define WAY    5
#define BLK    128
#define NBLK   10               // packed upper-tri 128x128 blocks of 4x4 grid
#define BLKSZ  (BLK * BLK)      // 16384 halves per block
#define KPACK  (NBLK * BLKSZ)   // 163840
#define PITCH  136              // smem pitch (halves) for X slices
#define SLICE  (FF * PITCH)     // halves per slice buffer
#define NUNIT_S (NBLK * NS)     // 250 support units
#define NUNIT_Q (NBLK * NQ)     // 2000 query units
#define GGRID  296              // persistent CTAs (2/SM)

// -------- scratch (__device__ globals; no allocations allowed) --------------
__device__ __half g_Sn[NS * FF * DD];        // 2 MB   normalized supports
__device__ __half g_Qn[NQ * FF * DD];        // 16.4MB normalized queries
__device__ __half g_Gs[NS][KPACK];           // per-support Grams, frag order (x2 offdiag)
__device__ __half g_Gp[WAY][KPACK];          // class-summed Grams, frag order (1.6MB)
__device__ float  g_bar[NITEM][DD];          // per-item feature-row sums
__device__ float  g_sbarsum[WAY][DD];
__device__ int    g_cls_cnt[WAY];
__device__ int    g_cls_sup[WAY][NS];
__device__ float  g_S2[WAY][NQ];

__constant__ int c_bi[NBLK] = {0,0,0,0,1,1,1,2,2,3};
__constant__ int c_bj[NBLK] = {0,1,2,3,1,2,3,2,3,3};

// ---------------------------------------------------------------------------
// K1 (fused): per-item normalize + rowsum. One CTA per item. (proven)
// ---------------------------------------------------------------------------
__global__ void __launch_bounds__(256) norm_kernel(
    const float* __restrict__ sg, const float* __restrict__ sl,
    const float* __restrict__ qg, const float* __restrict__ ql)
{
    __shared__ float snorm[FF];
    const int item = blockIdx.x;
    const int tid  = threadIdx.x;
    const int lane = tid & 31;
    const int warp = tid >> 5;

    const float* gbase;
    const float* lbase;
    __half* dst;
    if (item < NS) {
        gbase = sg + (size_t)item * 16 * DD;
        lbase = sl + (size_t)item * 64 * DD;
        dst   = g_Sn + (size_t)item * FF * DD;
    } else {
        int q = item - NS;
        gbase = qg + (size_t)q * 16 * DD;
        lbase = ql + (size_t)q * 64 * DD;
        dst   = g_Qn + (size_t)q * FF * DD;
    }

    for (int f = warp; f < FF; f += 8) {
        const float4* src = (const float4*)((f < 16) ? gbase + (size_t)f * DD
                                                     : lbase + (size_t)(f - 16) * DD);
        float ss = 0.f;
#pragma unroll
        for (int i = 0; i < 4; i++) {
            float4 v = src[lane + 32 * i];
            ss += v.x * v.x + v.y * v.y + v.z * v.z + v.w * v.w;
        }
#pragma unroll
        for (int o = 16; o; o >>= 1) ss += __shfl_xor_sync(0xFFFFFFFFu, ss, o);
        if (lane == 0) snorm[f] = rsqrtf(fmaxf(ss, 1e-24f));
    }
    __syncthreads();

    float sx = 0.f, sy = 0.f;
#pragma unroll 4
    for (int f = 0; f < FF; f++) {
        const float2* src = (const float2*)((f < 16) ? gbase + (size_t)f * DD
                                                     : lbase + (size_t)(f - 16) * DD);
        float2 v = src[tid];
        float rn = snorm[f];
        float a = v.x * rn, b = v.y * rn;
        sx += a; sy += b;
        *(__half2*)(dst + (size_t)f * DD + 2 * tid) = __floats2half2_rn(a, b);
    }
    g_bar[item][2 * tid + 0] = sx;
    g_bar[item][2 * tid + 1] = sy;
}

// ---------------------------------------------------------------------------
// K2: class lists/counts, class-summed row-sums, zero S2 (proven)
// ---------------------------------------------------------------------------
__global__ void prep_kernel(const long long* __restrict__ labels)
{
    __shared__ int cnt[WAY];
    __shared__ int sup[WAY][NS];
    int t = threadIdx.x;  // 512
    if (t == 0) {
        for (int c = 0; c < WAY; c++) cnt[c] = 0;
        for (int s = 0; s < NS; s++) {
            int c = (int)labels[s];
            sup[c][cnt[c]++] = s;
        }
        for (int c = 0; c < WAY; c++) {
            g_cls_cnt[c] = cnt[c];
            for (int i = 0; i < cnt[c]; i++) g_cls_sup[c][i] = sup[c][i];
        }
    }
    __syncthreads();
    if (t < DD) {
#pragma unroll
        for (int c = 0; c < WAY; c++) {
            float a = 0.f;
            for (int i = 0; i < cnt[c]; i++) a += g_bar[sup[c][i]][t];
            g_sbarsum[c][t] = a;
        }
    }
    for (int i = t; i < WAY * NQ; i += blockDim.x)
        (&g_S2[0][0])[i] = 0.f;
}

// ---------------------------------------------------------------------------
// shared mma machinery (proven)
// ---------------------------------------------------------------------------
__device__ __forceinline__ void ldsm_x4_t(uint32_t (&r)[4], const __half* p)
{
    uint32_t a = (uint32_t)__cvta_generic_to_shared(p);
    asm volatile("ldmatrix.sync.aligned.m8n8.x4.trans.shared.b16 {%0,%1,%2,%3}, [%4];"
                 : "=r"(r[0]), "=r"(r[1]), "=r"(r[2]), "=r"(r[3]) : "r"(a));
}

__device__ __forceinline__ void mma16816(float (&d)[4], const uint32_t (&a)[4],
                                         uint32_t b0, uint32_t b1)
{
    asm volatile("mma.sync.aligned.m16n8k16.row.col.f32.f16.f16.f32 "
                 "{%0,%1,%2,%3},{%4,%5,%6,%7},{%8,%9},{%0,%1,%2,%3};"
                 : "+f"(d[0]), "+f"(d[1]), "+f"(d[2]), "+f"(d[3])
                 : "r"(a[0]), "r"(a[1]), "r"(a[2]), "r"(a[3]), "r"(b0), "r"(b1));
}

__device__ __forceinline__ void gram_block_mma(
    const __half* sX0, const __half* pB, float (&acc)[2][8][4],
    int m_base, int n_base, int lane)
{
    const int a_krow = ((lane >> 4) << 3) + (lane & 7);
    const int a_coff = ((lane >> 3) & 1) << 3;
    const int b_krow = (((lane >> 3) & 1) << 3) + (lane & 7);
    const int b_coff = (lane >> 4) << 3;

#pragma unroll
    for (int k16 = 0; k16 < FF / 16; k16++) {
        const int k0 = k16 * 16;
        uint32_t a[2][4];
#pragma unroll
        for (int mt = 0; mt < 2; mt++)
            ldsm_x4_t(a[mt], &sX0[(k0 + a_krow) * PITCH + m_base + mt * 16 + a_coff]);
#pragma unroll
        for (int nt = 0; nt < 4; nt++) {
            uint32_t bf[4];
            ldsm_x4_t(bf, &pB[(k0 + b_krow) * PITCH + n_base + nt * 16 + b_coff]);
#pragma unroll
            for (int mt = 0; mt < 2; mt++) {
                mma16816(acc[mt][2 * nt + 0], a[mt], bf[0], bf[1]);
                mma16816(acc[mt][2 * nt + 1], a[mt], bf[2], bf[3]);
            }
        }
    }
}

extern __shared__ char dynsmem[];

__device__ __forceinline__ void issue_slice_load(
    const __half* base, int b, int stage, int tid)
{
    const int bi = c_bi[b], bj = c_bj[b];
    __half* s0 = (__half*)dynsmem + stage * 2 * SLICE;
    const int nch = (bi == bj) ? 1280 : 2560;
    for (int ch = tid; ch < nch; ch += 256) {
        int tile = (ch >= 1280) ? 1 : 0;
        int rem  = ch - tile * 1280;
        int r = rem >> 4, cc = rem & 15;
        int colblk = tile ? bj : bi;
        const __half* src = base + (size_t)r * DD + colblk * 128 + cc * 8;
        __half* dsts = s0 + tile * SLICE + r * PITCH + cc * 8;
        uint32_t dst = (uint32_t)__cvta_generic_to_shared(dsts);
        asm volatile("cp.async.cg.shared.global [%0], [%1], 16;" :: "r"(dst), "l"(src));
    }
    asm volatile("cp.async.commit_group;");
}

// ---------------------------------------------------------------------------
// K3: support Gram (persistent, R7 machinery). 250 units -> g_Gs.
// ---------------------------------------------------------------------------
__global__ void __launch_bounds__(256, 2) sgram_kernel()
{
    const int tid  = threadIdx.x;
    const int lane = tid & 31;
    const int warp = tid >> 5;
    const int m_base = (warp >> 1) * 32;
    const int n_base = (warp & 1) * 64;

    int u = blockIdx.x;
    if (u >= NUNIT_S) return;

    issue_slice_load(g_Sn + (size_t)(u / NBLK) * FF * DD, u % NBLK, 0, tid);
    int stage = 0;

    for (; u < NUNIT_S; u += gridDim.x) {
        const int nextu = u + gridDim.x;
        if (nextu < NUNIT_S) {
            issue_slice_load(g_Sn + (size_t)(nextu / NBLK) * FF * DD, nextu % NBLK,
                             stage ^ 1, tid);
            asm volatile("cp.async.wait_group 1;");
        } else {
            asm volatile("cp.async.wait_group 0;");
        }
        __syncthreads();

        const int item = u / NBLK, b = u % NBLK;
        const bool diag = (c_bi[b] == c_bj[b]);
        const __half* s0 = (const __half*)dynsmem + stage * 2 * SLICE;
        const __half* pB = diag ? s0 : s0 + SLICE;

        float acc[2][8][4];
#pragma unroll
        for (int mt = 0; mt < 2; mt++)
#pragma unroll
            for (int nt = 0; nt < 8; nt++)
#pragma unroll
                for (int i = 0; i < 4; i++) acc[mt][nt][i] = 0.f;

        gram_block_mma(s0, pB, acc, m_base, n_base, lane);

        const float scale = diag ? 1.f : 2.f;
        __half* out = g_Gs[item] + (size_t)b * BLKSZ;
#pragma unroll
        for (int j = 0; j < 8; j++) {
            const int mt = j >> 2, nt0 = (j & 3) * 2;
            __half2 h[4];
            h[0] = __floats2half2_rn(acc[mt][nt0][0] * scale, acc[mt][nt0][1] * scale);
            h[1] = __floats2half2_rn(acc[mt][nt0][2] * scale, acc[mt][nt0][3] * scale);
            h[2] = __floats2half2_rn(acc[mt][nt0 + 1][0] * scale, acc[mt][nt0 + 1][1] * scale);
            h[3] = __floats2half2_rn(acc[mt][nt0 + 1][2] * scale, acc[mt][nt0 + 1][3] * scale);
            *(int4*)(out + (size_t)(j * 256 + tid) * 8) = *(int4*)h;
        }
        __syncthreads();
        stage ^= 1;
    }
}

// ---------------------------------------------------------------------------
// K4: classsum v5 (proven 7.2us) — per-class CTAs, chain <=5.
// ---------------------------------------------------------------------------
__global__ void __launch_bounds__(256) classsum_kernel()
{
    const int c    = blockIdx.y;
    const int base = blockIdx.x * 1024 + threadIdx.x * 4;
    const int cnt  = g_cls_cnt[c];

    float a0 = 0.f, a1 = 0.f, a2 = 0.f, a3 = 0.f;
#pragma unroll 5
    for (int i = 0; i < cnt; i++) {
        uint2 v = *(const uint2*)&g_Gs[g_cls_sup[c][i]][base];
        float2 p0 = __half22float2(*(const __half2*)&v.x);
        float2 p1 = __half22float2(*(const __half2*)&v.y);
        a0 += p0.x; a1 += p0.y; a2 += p1.x; a3 += p1.y;
    }
    uint2 o;
    *(__half2*)&o.x = __floats2half2_rn(a0, a1);
    *(__half2*)&o.y = __floats2half2_rn(a2, a3);
    *(uint2*)&g_Gp[c][base] = o;
}

// ---------------------------------------------------------------------------
// K5: qdot — persistent pipelined query Gram with FUSED Frobenius dot.
// 2000 units = (query, block). H never materialized: each thread dots its
// fragment accumulators against the matching frag-ordered Gc slices (L2-
// resident, contiguous int4 per j), then butterfly + block reduce + atomics.
// ---------------------------------------------------------------------------
__global__ void __launch_bounds__(256, 2) qdot_kernel()
{
    __shared__ float red[8][WAY];

    const int tid  = threadIdx.x;
    const int lane = tid & 31;
    const int warp = tid >> 5;
    const int m_base = (warp >> 1) * 32;
    const int n_base = (warp & 1) * 64;

    int u = blockIdx.x;
    if (u >= NUNIT_Q) return;

    issue_slice_load(g_Qn + (size_t)(u / NBLK) * FF * DD, u % NBLK, 0, tid);
    int stage = 0;

    for (; u < NUNIT_Q; u += gridDim.x) {
        const int nextu = u + gridDim.x;
        if (nextu < NUNIT_Q) {
            issue_slice_load(g_Qn + (size_t)(nextu / NBLK) * FF * DD, nextu % NBLK,
                             stage ^ 1, tid);
            asm volatile("cp.async.wait_group 1;");
        } else {
            asm volatile("cp.async.wait_group 0;");
        }
        __syncthreads();

        const int q = u / NBLK, b = u % NBLK;
        const bool diag = (c_bi[b] == c_bj[b]);
        const __half* s0 = (const __half*)dynsmem + stage * 2 * SLICE;
        const __half* pB = diag ? s0 : s0 + SLICE;

        float acc[2][8][4];
#pragma unroll
        for (int mt = 0; mt < 2; mt++)
#pragma unroll
            for (int nt = 0; nt < 8; nt++)
#pragma unroll
                for (int i = 0; i < 4; i++) acc[mt][nt][i] = 0.f;

        gram_block_mma(s0, pB, acc, m_base, n_base, lane);

        // ---- fused Frobenius dot: acc (frag order) vs Gc slices (frag order)
        float part[WAY] = {0.f, 0.f, 0.f, 0.f, 0.f};
#pragma unroll
        for (int j = 0; j < 8; j++) {
            const int mt = j >> 2, nt0 = (j & 3) * 2;
            const size_t off = (size_t)b * BLKSZ + (size_t)(j * 256 + tid) * 8;
            const float v0 = acc[mt][nt0][0],     v1 = acc[mt][nt0][1];
            const float v2 = acc[mt][nt0][2],     v3 = acc[mt][nt0][3];
            const float v4 = acc[mt][nt0 + 1][0], v5 = acc[mt][nt0 + 1][1];
            const float v6 = acc[mt][nt0 + 1][2], v7 = acc[mt][nt0 + 1][3];
#pragma unroll
            for (int c = 0; c < WAY; c++) {
                int4 gv = *(const int4*)&g_Gp[c][off];
                const __half2* gh = (const __half2*)&gv;
                float2 g0 = __half22float2(gh[0]);
                float2 g1 = __half22float2(gh[1]);
                float2 g2 = __half22float2(gh[2]);
                float2 g3 = __half22float2(gh[3]);
                part[c] += v0 * g0.x + v1 * g0.y + v2 * g1.x + v3 * g1.y
                         + v4 * g2.x + v5 * g2.y + v6 * g3.x + v7 * g3.y;
            }
        }

#pragma unroll
        for (int o = 16; o; o >>= 1)
#pragma unroll
            for (int c = 0; c < WAY; c++)
                part[c] += __shfl_xor_sync(0xFFFFFFFFu, part[c], o);

        if (lane == 0)
#pragma unroll
            for (int c = 0; c < WAY; c++) red[warp][c] = part[c];
        __syncthreads();
        if (tid < WAY) {
            float s = 0.f;
#pragma unroll
            for (int w = 0; w < 8; w++) s += red[w][tid];
            atomicAdd(&g_S2[tid][q], s);
        }
        __syncthreads();
        stage ^= 1;
    }
}

// ---------------------------------------------------------------------------
// K6: logits (proven fast form)
// ---------------------------------------------------------------------------
__global__ void logits_kernel(float* __restrict__ out)
{
    int warp = (blockIdx.x * blockDim.x + threadIdx.x) >> 5;
    int lane = threadIdx.x & 31;
    if (warp >= NQ) return;
    const int q = warp;

    float s1[WAY] = {0.f, 0.f, 0.f, 0.f, 0.f};
    const float* qb = g_bar[NS + q];
    for (int k = lane; k < DD; k += 32) {
        float qv = qb[k];
#pragma unroll
        for (int c = 0; c < WAY; c++) s1[c] += g_sbarsum[c][k] * qv;
    }
#pragma unroll
    for (int o = 16; o; o >>= 1)
#pragma unroll
        for (int c = 0; c < WAY; c++)
            s1[c] += __shfl_xor_sync(0xFFFFFFFFu, s1[c], o);

    if (lane < WAY) {
        int c = lane;
        float cnt = (float)g_cls_cnt[c];
        out[q * WAY + c] = -2.f * (float)(FF * FF) + (4.f * s1[c] - 2.f * g_S2[c][q]) / cnt;
    }
}

// ---------------------------------------------------------------------------
extern "C" void kernel_launch(void* const* d_in, const int* in_sizes, int n_in,
                              void* d_out, int out_size)
{
    const float*     sg  = (const float*)d_in[0];
    const float*     sl  = (const float*)d_in[1];
    const long long* lab = (const long long*)d_in[2];
    const float*     qg  = (const float*)d_in[3];
    const float*     ql  = (const float*)d_in[4];
    float*           out = (float*)d_out;

    const int smem = 2 * 2 * SLICE * 2;   // 2 stages x 2 slices = 87040 B
    static bool attr_set = false;
    if (!attr_set) {
        cudaFuncSetAttribute(sgram_kernel, cudaFuncAttributeMaxDynamicSharedMemorySize, smem);
        cudaFuncSetAttribute(qdot_kernel,  cudaFuncAttributeMaxDynamicSharedMemorySize, smem);
        attr_set = true;
    }

    norm_kernel<<<NITEM, 256>>>(sg, sl, qg, ql);          // normalize + rowsum
    prep_kernel<<<1, 512>>>(lab);
    sgram_kernel<<<NUNIT_S, 256, smem>>>();               // 250 units -> g_Gs
    classsum_kernel<<<dim3(KPACK / 1024, WAY), 256>>>();  // 800 CTAs -> g_Gp
    qdot_kernel<<<GGRID, 256, smem>>>();                  // 2000 units, fused dot
    logits_kernel<<<(NQ * 32 + 255) / 256, 256>>>(out);
}

// round 15
// speedup vs baseline: 1.3159x; 1.1055x over previous
#include <cuda_runtime.h>
#include <cuda_fp16.h>
#include <cstdint>

#define NS     25
#define NQ     200
#define NITEM  (NS + NQ)        // 225
#define FF     80
#define DD     512
#define WAY    5
#define BLK    128
#define NBLK   10               // packed upper-tri 128x128 blocks of 4x4 grid
#define BLKSZ  (BLK * BLK)      // 16384 halves per block
#define KPACK  (NBLK * BLKSZ)   // 163840
#define PITCH  136              // smem pitch (halves) for X slices
#define SLICE  (FF * PITCH)     // halves per slice buffer
#define NUNIT_S (NBLK * NS)     // 250 support units
#define NUNIT_Q (NBLK * NQ)     // 2000 query units
#define GGRID  296              // persistent CTAs (2/SM)

// -------- scratch (__device__ globals; no allocations allowed) --------------
__device__ __half g_Sn[NS * FF * DD];        // 2 MB   normalized supports
__device__ __half g_Qn[NQ * FF * DD];        // 16.4MB normalized queries
__device__ __half g_Gs[NS][KPACK];           // per-support Grams, frag order (x2 offdiag)
__device__ __half g_Gp[WAY][KPACK];          // class-summed Grams, frag order (1.6MB)
__device__ float  g_bar[NITEM][DD];          // per-item feature-row sums
__device__ float  g_sbarsum[WAY][DD];
__device__ int    g_cls_cnt[WAY];
__device__ int    g_cls_sup[WAY][NS];
__device__ float  g_S2[WAY][NQ];

__constant__ int c_bi[NBLK] = {0,0,0,0,1,1,1,2,2,3};
__constant__ int c_bj[NBLK] = {0,1,2,3,1,2,3,2,3,3};

// ---------------------------------------------------------------------------
// K1 (fused): per-item normalize + rowsum. One CTA per item. (proven)
// ---------------------------------------------------------------------------
__global__ void __launch_bounds__(256) norm_kernel(
    const float* __restrict__ sg, const float* __restrict__ sl,
    const float* __restrict__ qg, const float* __restrict__ ql)
{
    __shared__ float snorm[FF];
    const int item = blockIdx.x;
    const int tid  = threadIdx.x;
    const int lane = tid & 31;
    const int warp = tid >> 5;

    const float* gbase;
    const float* lbase;
    __half* dst;
    if (item < NS) {
        gbase = sg + (size_t)item * 16 * DD;
        lbase = sl + (size_t)item * 64 * DD;
        dst   = g_Sn + (size_t)item * FF * DD;
    } else {
        int q = item - NS;
        gbase = qg + (size_t)q * 16 * DD;
        lbase = ql + (size_t)q * 64 * DD;
        dst   = g_Qn + (size_t)q * FF * DD;
    }

    for (int f = warp; f < FF; f += 8) {
        const float4* src = (const float4*)((f < 16) ? gbase + (size_t)f * DD
                                                     : lbase + (size_t)(f - 16) * DD);
        float ss = 0.f;
#pragma unroll
        for (int i = 0; i < 4; i++) {
            float4 v = src[lane + 32 * i];
            ss += v.x * v.x + v.y * v.y + v.z * v.z + v.w * v.w;
        }
#pragma unroll
        for (int o = 16; o; o >>= 1) ss += __shfl_xor_sync(0xFFFFFFFFu, ss, o);
        if (lane == 0) snorm[f] = rsqrtf(fmaxf(ss, 1e-24f));
    }
    __syncthreads();

    float sx = 0.f, sy = 0.f;
#pragma unroll 4
    for (int f = 0; f < FF; f++) {
        const float2* src = (const float2*)((f < 16) ? gbase + (size_t)f * DD
                                                     : lbase + (size_t)(f - 16) * DD);
        float2 v = src[tid];
        float rn = snorm[f];
        float a = v.x * rn, b = v.y * rn;
        sx += a; sy += b;
        *(__half2*)(dst + (size_t)f * DD + 2 * tid) = __floats2half2_rn(a, b);
    }
    g_bar[item][2 * tid + 0] = sx;
    g_bar[item][2 * tid + 1] = sy;
}

// ---------------------------------------------------------------------------
// K2: class lists/counts, class-summed row-sums, zero S2 (proven)
// ---------------------------------------------------------------------------
__global__ void prep_kernel(const long long* __restrict__ labels)
{
    __shared__ int cnt[WAY];
    __shared__ int sup[WAY][NS];
    int t = threadIdx.x;  // 512
    if (t == 0) {
        for (int c = 0; c < WAY; c++) cnt[c] = 0;
        for (int s = 0; s < NS; s++) {
            int c = (int)labels[s];
            sup[c][cnt[c]++] = s;
        }
        for (int c = 0; c < WAY; c++) {
            g_cls_cnt[c] = cnt[c];
            for (int i = 0; i < cnt[c]; i++) g_cls_sup[c][i] = sup[c][i];
        }
    }
    __syncthreads();
    if (t < DD) {
#pragma unroll
        for (int c = 0; c < WAY; c++) {
            float a = 0.f;
            for (int i = 0; i < cnt[c]; i++) a += g_bar[sup[c][i]][t];
            g_sbarsum[c][t] = a;
        }
    }
    for (int i = t; i < WAY * NQ; i += blockDim.x)
        (&g_S2[0][0])[i] = 0.f;
}

// ---------------------------------------------------------------------------
// shared mma machinery — fp16 accumulators
// ---------------------------------------------------------------------------
__device__ __forceinline__ void ldsm_x4_t(uint32_t (&r)[4], const __half* p)
{
    uint32_t a = (uint32_t)__cvta_generic_to_shared(p);
    asm volatile("ldmatrix.sync.aligned.m8n8.x4.trans.shared.b16 {%0,%1,%2,%3}, [%4];"
                 : "=r"(r[0]), "=r"(r[1]), "=r"(r[2]), "=r"(r[3]) : "r"(a));
}

__device__ __forceinline__ void mma16816h(uint32_t (&d)[2], const uint32_t (&a)[4],
                                          uint32_t b0, uint32_t b1)
{
    asm volatile("mma.sync.aligned.m16n8k16.row.col.f16.f16.f16.f16 "
                 "{%0,%1},{%2,%3,%4,%5},{%6,%7},{%0,%1};"
                 : "+r"(d[0]), "+r"(d[1])
                 : "r"(a[0]), "r"(a[1]), "r"(a[2]), "r"(a[3]), "r"(b0), "r"(b1));
}

// acc_h[mt][nt][slot]: slot0 = (row, col..col+1), slot1 = (row+8, col..col+1)
__device__ __forceinline__ void gram_block_mma_h(
    const __half* sX0, const __half* pB, uint32_t (&acc)[2][8][2],
    int m_base, int n_base, int lane)
{
    const int a_krow = ((lane >> 4) << 3) + (lane & 7);
    const int a_coff = ((lane >> 3) & 1) << 3;
    const int b_krow = (((lane >> 3) & 1) << 3) + (lane & 7);
    const int b_coff = (lane >> 4) << 3;

#pragma unroll
    for (int k16 = 0; k16 < FF / 16; k16++) {
        const int k0 = k16 * 16;
        uint32_t a[2][4];
#pragma unroll
        for (int mt = 0; mt < 2; mt++)
            ldsm_x4_t(a[mt], &sX0[(k0 + a_krow) * PITCH + m_base + mt * 16 + a_coff]);
#pragma unroll
        for (int nt = 0; nt < 4; nt++) {
            uint32_t bf[4];
            ldsm_x4_t(bf, &pB[(k0 + b_krow) * PITCH + n_base + nt * 16 + b_coff]);
#pragma unroll
            for (int mt = 0; mt < 2; mt++) {
                mma16816h(acc[mt][2 * nt + 0], a[mt], bf[0], bf[1]);
                mma16816h(acc[mt][2 * nt + 1], a[mt], bf[2], bf[3]);
            }
        }
    }
}

extern __shared__ char dynsmem[];

__device__ __forceinline__ void issue_slice_load(
    const __half* base, int b, int stage, int tid)
{
    const int bi = c_bi[b], bj = c_bj[b];
    __half* s0 = (__half*)dynsmem + stage * 2 * SLICE;
    const int nch = (bi == bj) ? 1280 : 2560;
    for (int ch = tid; ch < nch; ch += 256) {
        int tile = (ch >= 1280) ? 1 : 0;
        int rem  = ch - tile * 1280;
        int r = rem >> 4, cc = rem & 15;
        int colblk = tile ? bj : bi;
        const __half* src = base + (size_t)r * DD + colblk * 128 + cc * 8;
        __half* dsts = s0 + tile * SLICE + r * PITCH + cc * 8;
        uint32_t dst = (uint32_t)__cvta_generic_to_shared(dsts);
        asm volatile("cp.async.cg.shared.global [%0], [%1], 16;" :: "r"(dst), "l"(src));
    }
    asm volatile("cp.async.commit_group;");
}

// ---------------------------------------------------------------------------
// K3: support Gram (persistent, fp16 acc). 250 units -> g_Gs (frag order).
// ---------------------------------------------------------------------------
__global__ void __launch_bounds__(256, 2) sgram_kernel()
{
    const int tid  = threadIdx.x;
    const int lane = tid & 31;
    const int warp = tid >> 5;
    const int m_base = (warp >> 1) * 32;
    const int n_base = (warp & 1) * 64;

    int u = blockIdx.x;
    if (u >= NUNIT_S) return;

    issue_slice_load(g_Sn + (size_t)(u / NBLK) * FF * DD, u % NBLK, 0, tid);
    int stage = 0;

    for (; u < NUNIT_S; u += gridDim.x) {
        const int nextu = u + gridDim.x;
        if (nextu < NUNIT_S) {
            issue_slice_load(g_Sn + (size_t)(nextu / NBLK) * FF * DD, nextu % NBLK,
                             stage ^ 1, tid);
            asm volatile("cp.async.wait_group 1;");
        } else {
            asm volatile("cp.async.wait_group 0;");
        }
        __syncthreads();

        const int item = u / NBLK, b = u % NBLK;
        const bool diag = (c_bi[b] == c_bj[b]);
        const __half* s0 = (const __half*)dynsmem + stage * 2 * SLICE;
        const __half* pB = diag ? s0 : s0 + SLICE;

        uint32_t acc[2][8][2];
#pragma unroll
        for (int mt = 0; mt < 2; mt++)
#pragma unroll
            for (int nt = 0; nt < 8; nt++)
                acc[mt][nt][0] = acc[mt][nt][1] = 0u;

        gram_block_mma_h(s0, pB, acc, m_base, n_base, lane);

        const __half2 two2 = __floats2half2_rn(2.f, 2.f);
        __half* out = g_Gs[item] + (size_t)b * BLKSZ;
#pragma unroll
        for (int j = 0; j < 8; j++) {
            const int mt = j >> 2, nt0 = (j & 3) * 2;
            uint32_t h[4] = {acc[mt][nt0][0], acc[mt][nt0][1],
                             acc[mt][nt0 + 1][0], acc[mt][nt0 + 1][1]};
            if (!diag) {
#pragma unroll
                for (int k = 0; k < 4; k++) {
                    __half2 v = __hmul2(*(__half2*)&h[k], two2);
                    h[k] = *(uint32_t*)&v;
                }
            }
            *(int4*)(out + (size_t)(j * 256 + tid) * 8) = *(int4*)h;
        }
        __syncthreads();
        stage ^= 1;
    }
}

// ---------------------------------------------------------------------------
// K4: classsum — per-class CTAs, int4 wide (8 halves/thread), fp32 accumulate.
// grid (KPACK/2048 = 80, WAY) = 400 CTAs.
// ---------------------------------------------------------------------------
__global__ void __launch_bounds__(256) classsum_kernel()
{
    const int c    = blockIdx.y;
    const int base = blockIdx.x * 2048 + threadIdx.x * 8;
    const int cnt  = g_cls_cnt[c];

    float acc[8];
#pragma unroll
    for (int i = 0; i < 8; i++) acc[i] = 0.f;

#pragma unroll 5
    for (int i = 0; i < cnt; i++) {
        int4 v = *(const int4*)&g_Gs[g_cls_sup[c][i]][base];
        const __half2* h = (const __half2*)&v;
#pragma unroll
        for (int j = 0; j < 4; j++) {
            float2 p = __half22float2(h[j]);
            acc[2 * j + 0] += p.x;
            acc[2 * j + 1] += p.y;
        }
    }
    __half2 o[4];
#pragma unroll
    for (int j = 0; j < 4; j++) o[j] = __floats2half2_rn(acc[2 * j], acc[2 * j + 1]);
    *(int4*)&g_Gp[c][base] = *(int4*)o;
}

// ---------------------------------------------------------------------------
// K5: qdot — persistent pipelined query Gram (fp16 acc) with fused HFMA2
// Frobenius dot vs frag-ordered Gc slices. 2000 units.
// ---------------------------------------------------------------------------
__global__ void __launch_bounds__(256, 2) qdot_kernel()
{
    __shared__ float red[8][WAY];

    const int tid  = threadIdx.x;
    const int lane = tid & 31;
    const int warp = tid >> 5;
    const int m_base = (warp >> 1) * 32;
    const int n_base = (warp & 1) * 64;

    int u = blockIdx.x;
    if (u >= NUNIT_Q) return;

    issue_slice_load(g_Qn + (size_t)(u / NBLK) * FF * DD, u % NBLK, 0, tid);
    int stage = 0;

    for (; u < NUNIT_Q; u += gridDim.x) {
        const int nextu = u + gridDim.x;
        if (nextu < NUNIT_Q) {
            issue_slice_load(g_Qn + (size_t)(nextu / NBLK) * FF * DD, nextu % NBLK,
                             stage ^ 1, tid);
            asm volatile("cp.async.wait_group 1;");
        } else {
            asm volatile("cp.async.wait_group 0;");
        }
        __syncthreads();

        const int q = u / NBLK, b = u % NBLK;
        const bool diag = (c_bi[b] == c_bj[b]);
        const __half* s0 = (const __half*)dynsmem + stage * 2 * SLICE;
        const __half* pB = diag ? s0 : s0 + SLICE;

        uint32_t acc[2][8][2];
#pragma unroll
        for (int mt = 0; mt < 2; mt++)
#pragma unroll
            for (int nt = 0; nt < 8; nt++)
                acc[mt][nt][0] = acc[mt][nt][1] = 0u;

        gram_block_mma_h(s0, pB, acc, m_base, n_base, lane);

        // ---- fused HFMA2 Frobenius dot: acc (half2 frag) vs Gc (frag order)
        __half2 hacc[WAY];
#pragma unroll
        for (int c = 0; c < WAY; c++) hacc[c] = __floats2half2_rn(0.f, 0.f);

#pragma unroll
        for (int j = 0; j < 8; j++) {
            const int mt = j >> 2, nt0 = (j & 3) * 2;
            const size_t off = (size_t)b * BLKSZ + (size_t)(j * 256 + tid) * 8;
            const __half2 a0 = *(const __half2*)&acc[mt][nt0][0];
            const __half2 a1 = *(const __half2*)&acc[mt][nt0][1];
            const __half2 a2 = *(const __half2*)&acc[mt][nt0 + 1][0];
            const __half2 a3 = *(const __half2*)&acc[mt][nt0 + 1][1];
#pragma unroll
            for (int c = 0; c < WAY; c++) {
                int4 gv = *(const int4*)&g_Gp[c][off];
                const __half2* gh = (const __half2*)&gv;
                hacc[c] = __hfma2(gh[0], a0, hacc[c]);
                hacc[c] = __hfma2(gh[1], a1, hacc[c]);
                hacc[c] = __hfma2(gh[2], a2, hacc[c]);
                hacc[c] = __hfma2(gh[3], a3, hacc[c]);
            }
        }

        float part[WAY];
#pragma unroll
        for (int c = 0; c < WAY; c++) {
            float2 f = __half22float2(hacc[c]);
            part[c] = f.x + f.y;
        }

#pragma unroll
        for (int o = 16; o; o >>= 1)
#pragma unroll
            for (int c = 0; c < WAY; c++)
                part[c] += __shfl_xor_sync(0xFFFFFFFFu, part[c], o);

        if (lane == 0)
#pragma unroll
            for (int c = 0; c < WAY; c++) red[warp][c] = part[c];
        __syncthreads();
        if (tid < WAY) {
            float s = 0.f;
#pragma unroll
            for (int w = 0; w < 8; w++) s += red[w][tid];
            atomicAdd(&g_S2[tid][q], s);
        }
        __syncthreads();
        stage ^= 1;
    }
}

// ---------------------------------------------------------------------------
// K6: logits (proven fast form)
// ---------------------------------------------------------------------------
__global__ void logits_kernel(float* __restrict__ out)
{
    int warp = (blockIdx.x * blockDim.x + threadIdx.x) >> 5;
    int lane = threadIdx.x & 31;
    if (warp >= NQ) return;
    const int q = warp;

    float s1[WAY] = {0.f, 0.f, 0.f, 0.f, 0.f};
    const float* qb = g_bar[NS + q];
    for (int k = lane; k < DD; k += 32) {
        float qv = qb[k];
#pragma unroll
        for (int c = 0; c < WAY; c++) s1[c] += g_sbarsum[c][k] * qv;
    }
#pragma unroll
    for (int o = 16; o; o >>= 1)
#pragma unroll
        for (int c = 0; c < WAY; c++)
            s1[c] += __shfl_xor_sync(0xFFFFFFFFu, s1[c], o);

    if (lane < WAY) {
        int c = lane;
        float cnt = (float)g_cls_cnt[c];
        out[q * WAY + c] = -2.f * (float)(FF * FF) + (4.f * s1[c] - 2.f * g_S2[c][q]) / cnt;
    }
}

// ---------------------------------------------------------------------------
extern "C" void kernel_launch(void* const* d_in, const int* in_sizes, int n_in,
                              void* d_out, int out_size)
{
    const float*     sg  = (const float*)d_in[0];
    const float*     sl  = (const float*)d_in[1];
    const long long* lab = (const long long*)d_in[2];
    const float*     qg  = (const float*)d_in[3];
    const float*     ql  = (const float*)d_in[4];
    float*           out = (float*)d_out;

    const int smem = 2 * 2 * SLICE * 2;   // 2 stages x 2 slices = 87040 B
    static bool attr_set = false;
    if (!attr_set) {
        cudaFuncSetAttribute(sgram_kernel, cudaFuncAttributeMaxDynamicSharedMemorySize, smem);
        cudaFuncSetAttribute(qdot_kernel,  cudaFuncAttributeMaxDynamicSharedMemorySize, smem);
        attr_set = true;
    }

    norm_kernel<<<NITEM, 256>>>(sg, sl, qg, ql);          // normalize + rowsum
    prep_kernel<<<1, 512>>>(lab);
    sgram_kernel<<<NUNIT_S, 256, smem>>>();               // 250 units -> g_Gs
    classsum_kernel<<<dim3(KPACK / 2048, WAY), 256>>>();  // 400 CTAs -> g_Gp
    qdot_kernel<<<GGRID, 256, smem>>>();                  // 2000 units, fused dot
    logits_kernel<<<(NQ * 32 + 255) / 256, 256>>>(out);
}

// round 16
// speedup vs baseline: 1.4482x; 1.1006x over previous
#include <cuda_runtime.h>
#include <cuda_fp16.h>
#include <cstdint>

#define NS     25
#define NQ     200
#define NITEM  (NS + NQ)        // 225
#define FF     80
#define DD     512
#define WAY    5
#define BLK    128
#define NBLK   10               // packed upper-tri 128x128 blocks of 4x4 grid
#define BLKSZ  (BLK * BLK)      // 16384 halves per block
#define KPACK  (NBLK * BLKSZ)   // 163840
#define PITCH  136              // smem pitch (halves) for X slices
#define SLICE  (FF * PITCH)     // halves per slice buffer
#define NUNIT_S (NBLK * NS)     // 250 support units
#define NPAIR   (NQ / 2)        // 100 query pairs
#define NUNIT_P (NBLK * NPAIR)  // 1000 paired query units
#define GGRID  296              // persistent CTAs (2/SM)

// -------- scratch (__device__ globals; no allocations allowed) --------------
__device__ __half g_Sn[NS * FF * DD];        // 2 MB   normalized supports
__device__ __half g_Qn[NQ * FF * DD];        // 16.4MB normalized queries
__device__ __half g_Gs[NS][KPACK];           // per-support Grams, frag order (x2 offdiag)
__device__ __half g_Gp[WAY][KPACK];          // class-summed Grams, frag order (1.6MB)
__device__ float  g_bar[NITEM][DD];          // per-item feature-row sums
__device__ float  g_sbarsum[WAY][DD];
__device__ int    g_cls_cnt[WAY];
__device__ int    g_cls_sup[WAY][NS];
__device__ float  g_S2[WAY][NQ];

__constant__ int c_bi[NBLK] = {0,0,0,0,1,1,1,2,2,3};
__constant__ int c_bj[NBLK] = {0,1,2,3,1,2,3,2,3,3};

// ---------------------------------------------------------------------------
// K1 (fused): per-item normalize + rowsum. One CTA per item. (proven)
// ---------------------------------------------------------------------------
__global__ void __launch_bounds__(256) norm_kernel(
    const float* __restrict__ sg, const float* __restrict__ sl,
    const float* __restrict__ qg, const float* __restrict__ ql)
{
    __shared__ float snorm[FF];
    const int item = blockIdx.x;
    const int tid  = threadIdx.x;
    const int lane = tid & 31;
    const int warp = tid >> 5;

    const float* gbase;
    const float* lbase;
    __half* dst;
    if (item < NS) {
        gbase = sg + (size_t)item * 16 * DD;
        lbase = sl + (size_t)item * 64 * DD;
        dst   = g_Sn + (size_t)item * FF * DD;
    } else {
        int q = item - NS;
        gbase = qg + (size_t)q * 16 * DD;
        lbase = ql + (size_t)q * 64 * DD;
        dst   = g_Qn + (size_t)q * FF * DD;
    }

    for (int f = warp; f < FF; f += 8) {
        const float4* src = (const float4*)((f < 16) ? gbase + (size_t)f * DD
                                                     : lbase + (size_t)(f - 16) * DD);
        float ss = 0.f;
#pragma unroll
        for (int i = 0; i < 4; i++) {
            float4 v = src[lane + 32 * i];
            ss += v.x * v.x + v.y * v.y + v.z * v.z + v.w * v.w;
        }
#pragma unroll
        for (int o = 16; o; o >>= 1) ss += __shfl_xor_sync(0xFFFFFFFFu, ss, o);
        if (lane == 0) snorm[f] = rsqrtf(fmaxf(ss, 1e-24f));
    }
    __syncthreads();

    float sx = 0.f, sy = 0.f;
#pragma unroll 4
    for (int f = 0; f < FF; f++) {
        const float2* src = (const float2*)((f < 16) ? gbase + (size_t)f * DD
                                                     : lbase + (size_t)(f - 16) * DD);
        float2 v = src[tid];
        float rn = snorm[f];
        float a = v.x * rn, b = v.y * rn;
        sx += a; sy += b;
        *(__half2*)(dst + (size_t)f * DD + 2 * tid) = __floats2half2_rn(a, b);
    }
    g_bar[item][2 * tid + 0] = sx;
    g_bar[item][2 * tid + 1] = sy;
}

// ---------------------------------------------------------------------------
// K2: class lists/counts, class-summed row-sums, zero S2 (proven)
// ---------------------------------------------------------------------------
__global__ void prep_kernel(const long long* __restrict__ labels)
{
    __shared__ int cnt[WAY];
    __shared__ int sup[WAY][NS];
    int t = threadIdx.x;  // 512
    if (t == 0) {
        for (int c = 0; c < WAY; c++) cnt[c] = 0;
        for (int s = 0; s < NS; s++) {
            int c = (int)labels[s];
            sup[c][cnt[c]++] = s;
        }
        for (int c = 0; c < WAY; c++) {
            g_cls_cnt[c] = cnt[c];
            for (int i = 0; i < cnt[c]; i++) g_cls_sup[c][i] = sup[c][i];
        }
    }
    __syncthreads();
    if (t < DD) {
#pragma unroll
        for (int c = 0; c < WAY; c++) {
            float a = 0.f;
            for (int i = 0; i < cnt[c]; i++) a += g_bar[sup[c][i]][t];
            g_sbarsum[c][t] = a;
        }
    }
    for (int i = t; i < WAY * NQ; i += blockDim.x)
        (&g_S2[0][0])[i] = 0.f;
}

// ---------------------------------------------------------------------------
// shared mma machinery — fp16 accumulators (proven R15)
// ---------------------------------------------------------------------------
__device__ __forceinline__ void ldsm_x4_t(uint32_t (&r)[4], const __half* p)
{
    uint32_t a = (uint32_t)__cvta_generic_to_shared(p);
    asm volatile("ldmatrix.sync.aligned.m8n8.x4.trans.shared.b16 {%0,%1,%2,%3}, [%4];"
                 : "=r"(r[0]), "=r"(r[1]), "=r"(r[2]), "=r"(r[3]) : "r"(a));
}

__device__ __forceinline__ void mma16816h(uint32_t (&d)[2], const uint32_t (&a)[4],
                                          uint32_t b0, uint32_t b1)
{
    asm volatile("mma.sync.aligned.m16n8k16.row.col.f16.f16.f16.f16 "
                 "{%0,%1},{%2,%3,%4,%5},{%6,%7},{%0,%1};"
                 : "+r"(d[0]), "+r"(d[1])
                 : "r"(a[0]), "r"(a[1]), "r"(a[2]), "r"(a[3]), "r"(b0), "r"(b1));
}

__device__ __forceinline__ void gram_block_mma_h(
    const __half* sX0, const __half* pB, uint32_t (&acc)[2][8][2],
    int m_base, int n_base, int lane)
{
    const int a_krow = ((lane >> 4) << 3) + (lane & 7);
    const int a_coff = ((lane >> 3) & 1) << 3;
    const int b_krow = (((lane >> 3) & 1) << 3) + (lane & 7);
    const int b_coff = (lane >> 4) << 3;

#pragma unroll
    for (int k16 = 0; k16 < FF / 16; k16++) {
        const int k0 = k16 * 16;
        uint32_t a[2][4];
#pragma unroll
        for (int mt = 0; mt < 2; mt++)
            ldsm_x4_t(a[mt], &sX0[(k0 + a_krow) * PITCH + m_base + mt * 16 + a_coff]);
#pragma unroll
        for (int nt = 0; nt < 4; nt++) {
            uint32_t bf[4];
            ldsm_x4_t(bf, &pB[(k0 + b_krow) * PITCH + n_base + nt * 16 + b_coff]);
#pragma unroll
            for (int mt = 0; mt < 2; mt++) {
                mma16816h(acc[mt][2 * nt + 0], a[mt], bf[0], bf[1]);
                mma16816h(acc[mt][2 * nt + 1], a[mt], bf[2], bf[3]);
            }
        }
    }
}

extern __shared__ char dynsmem[];

// stage in {0,1}: each stage holds 2 slices
__device__ __forceinline__ void issue_slice_load(
    const __half* base, int b, int stage, int tid)
{
    const int bi = c_bi[b], bj = c_bj[b];
    __half* s0 = (__half*)dynsmem + stage * 2 * SLICE;
    const int nch = (bi == bj) ? 1280 : 2560;
    for (int ch = tid; ch < nch; ch += 256) {
        int tile = (ch >= 1280) ? 1 : 0;
        int rem  = ch - tile * 1280;
        int r = rem >> 4, cc = rem & 15;
        int colblk = tile ? bj : bi;
        const __half* src = base + (size_t)r * DD + colblk * 128 + cc * 8;
        __half* dsts = s0 + tile * SLICE + r * PITCH + cc * 8;
        uint32_t dst = (uint32_t)__cvta_generic_to_shared(dsts);
        asm volatile("cp.async.cg.shared.global [%0], [%1], 16;" :: "r"(dst), "l"(src));
    }
    asm volatile("cp.async.commit_group;");
}

// ---------------------------------------------------------------------------
// K3: support Gram (persistent, fp16 acc, proven). 250 units -> g_Gs.
// ---------------------------------------------------------------------------
__global__ void __launch_bounds__(256, 2) sgram_kernel()
{
    const int tid  = threadIdx.x;
    const int lane = tid & 31;
    const int warp = tid >> 5;
    const int m_base = (warp >> 1) * 32;
    const int n_base = (warp & 1) * 64;

    int u = blockIdx.x;
    if (u >= NUNIT_S) return;

    issue_slice_load(g_Sn + (size_t)(u / NBLK) * FF * DD, u % NBLK, 0, tid);
    int stage = 0;

    for (; u < NUNIT_S; u += gridDim.x) {
        const int nextu = u + gridDim.x;
        if (nextu < NUNIT_S) {
            issue_slice_load(g_Sn + (size_t)(nextu / NBLK) * FF * DD, nextu % NBLK,
                             stage ^ 1, tid);
            asm volatile("cp.async.wait_group 1;");
        } else {
            asm volatile("cp.async.wait_group 0;");
        }
        __syncthreads();

        const int item = u / NBLK, b = u % NBLK;
        const bool diag = (c_bi[b] == c_bj[b]);
        const __half* s0 = (const __half*)dynsmem + stage * 2 * SLICE;
        const __half* pB = diag ? s0 : s0 + SLICE;

        uint32_t acc[2][8][2];
#pragma unroll
        for (int mt = 0; mt < 2; mt++)
#pragma unroll
            for (int nt = 0; nt < 8; nt++)
                acc[mt][nt][0] = acc[mt][nt][1] = 0u;

        gram_block_mma_h(s0, pB, acc, m_base, n_base, lane);

        const __half2 two2 = __floats2half2_rn(2.f, 2.f);
        __half* out = g_Gs[item] + (size_t)b * BLKSZ;
#pragma unroll
        for (int j = 0; j < 8; j++) {
            const int mt = j >> 2, nt0 = (j & 3) * 2;
            uint32_t h[4] = {acc[mt][nt0][0], acc[mt][nt0][1],
                             acc[mt][nt0 + 1][0], acc[mt][nt0 + 1][1]};
            if (!diag) {
#pragma unroll
                for (int k = 0; k < 4; k++) {
                    __half2 v = __hmul2(*(__half2*)&h[k], two2);
                    h[k] = *(uint32_t*)&v;
                }
            }
            *(int4*)(out + (size_t)(j * 256 + tid) * 8) = *(int4*)h;
        }
        __syncthreads();
        stage ^= 1;
    }
}

// ---------------------------------------------------------------------------
// K4: classsum v5 EXACT (R13-measured 7.2us): per-class CTAs, uint2 width,
// grid (160, 5) = 800 CTAs.
// ---------------------------------------------------------------------------
__global__ void __launch_bounds__(256) classsum_kernel()
{
    const int c    = blockIdx.y;
    const int base = blockIdx.x * 1024 + threadIdx.x * 4;   // 4 halves/thread
    const int cnt  = g_cls_cnt[c];

    float a0 = 0.f, a1 = 0.f, a2 = 0.f, a3 = 0.f;
#pragma unroll 5
    for (int i = 0; i < cnt; i++) {
        uint2 v = *(const uint2*)&g_Gs[g_cls_sup[c][i]][base];
        float2 p0 = __half22float2(*(const __half2*)&v.x);
        float2 p1 = __half22float2(*(const __half2*)&v.y);
        a0 += p0.x; a1 += p0.y; a2 += p1.x; a3 += p1.y;
    }
    uint2 o;
    *(__half2*)&o.x = __floats2half2_rn(a0, a1);
    *(__half2*)&o.y = __floats2half2_rn(a2, a3);
    *(uint2*)&g_Gp[c][base] = o;
}

// ---------------------------------------------------------------------------
// K5: qdot-pair — persistent; unit = (block b, query pair). Two query grams
// per unit share ONE pass over the Gc fragment slices (halves Gc L2 traffic).
// Straight-line 2-member pipeline (fixed trip count).
// ---------------------------------------------------------------------------
__global__ void __launch_bounds__(256, 2) qdot_kernel()
{
    __shared__ float red[8][2][WAY];

    const int tid  = threadIdx.x;
    const int lane = tid & 31;
    const int warp = tid >> 5;
    const int m_base = (warp >> 1) * 32;
    const int n_base = (warp & 1) * 64;

    int u = blockIdx.x;
    if (u >= NUNIT_P) return;

    // prologue: load q0 slices of first unit into buf0
    {
        const int b = u % NBLK, pair = u / NBLK;
        issue_slice_load(g_Qn + (size_t)(2 * pair) * FF * DD, b, 0, tid);
    }

    for (; u < NUNIT_P; u += gridDim.x) {
        const int b = u % NBLK, pair = u / NBLK;
        const bool diag = (c_bi[b] == c_bj[b]);
        const int q0 = 2 * pair;

        // issue q1 -> buf1; wait for q0 (all but last group)
        issue_slice_load(g_Qn + (size_t)(q0 + 1) * FF * DD, b, 1, tid);
        asm volatile("cp.async.wait_group 1;");
        __syncthreads();

        uint32_t acc0[2][8][2], acc1[2][8][2];
#pragma unroll
        for (int mt = 0; mt < 2; mt++)
#pragma unroll
            for (int nt = 0; nt < 8; nt++) {
                acc0[mt][nt][0] = acc0[mt][nt][1] = 0u;
                acc1[mt][nt][0] = acc1[mt][nt][1] = 0u;
            }

        {   // member 0 mma from buf0
            const __half* s0 = (const __half*)dynsmem;
            const __half* pB = diag ? s0 : s0 + SLICE;
            gram_block_mma_h(s0, pB, acc0, m_base, n_base, lane);
        }
        __syncthreads();   // buf0 free

        // prefetch next unit's q0 -> buf0; wait for q1
        const int nu = u + gridDim.x;
        if (nu < NUNIT_P) {
            issue_slice_load(g_Qn + (size_t)(2 * (nu / NBLK)) * FF * DD,
                             nu % NBLK, 0, tid);
            asm volatile("cp.async.wait_group 1;");
        } else {
            asm volatile("cp.async.wait_group 0;");
        }
        __syncthreads();

        {   // member 1 mma from buf1
            const __half* s1 = (const __half*)dynsmem + 2 * SLICE;
            const __half* pB = diag ? s1 : s1 + SLICE;
            gram_block_mma_h(s1, pB, acc1, m_base, n_base, lane);
        }

        // ---- fused dot: ONE Gc pass serves both accumulator sets ----
        __half2 h0[WAY], h1[WAY];
#pragma unroll
        for (int c = 0; c < WAY; c++) {
            h0[c] = __floats2half2_rn(0.f, 0.f);
            h1[c] = __floats2half2_rn(0.f, 0.f);
        }
#pragma unroll
        for (int j = 0; j < 8; j++) {
            const int mt = j >> 2, nt0 = (j & 3) * 2;
            const size_t off = (size_t)b * BLKSZ + (size_t)(j * 256 + tid) * 8;
            const __half2 a00 = *(const __half2*)&acc0[mt][nt0][0];
            const __half2 a01 = *(const __half2*)&acc0[mt][nt0][1];
            const __half2 a02 = *(const __half2*)&acc0[mt][nt0 + 1][0];
            const __half2 a03 = *(const __half2*)&acc0[mt][nt0 + 1][1];
            const __half2 a10 = *(const __half2*)&acc1[mt][nt0][0];
            const __half2 a11 = *(const __half2*)&acc1[mt][nt0][1];
            const __half2 a12 = *(const __half2*)&acc1[mt][nt0 + 1][0];
            const __half2 a13 = *(const __half2*)&acc1[mt][nt0 + 1][1];
#pragma unroll
            for (int c = 0; c < WAY; c++) {
                int4 gv = *(const int4*)&g_Gp[c][off];
                const __half2* gh = (const __half2*)&gv;
                h0[c] = __hfma2(gh[0], a00, h0[c]);
                h1[c] = __hfma2(gh[0], a10, h1[c]);
                h0[c] = __hfma2(gh[1], a01, h0[c]);
                h1[c] = __hfma2(gh[1], a11, h1[c]);
                h0[c] = __hfma2(gh[2], a02, h0[c]);
                h1[c] = __hfma2(gh[2], a12, h1[c]);
                h0[c] = __hfma2(gh[3], a03, h0[c]);
                h1[c] = __hfma2(gh[3], a13, h1[c]);
            }
        }

        float p0[WAY], p1[WAY];
#pragma unroll
        for (int c = 0; c < WAY; c++) {
            float2 f0 = __half22float2(h0[c]);
            float2 f1 = __half22float2(h1[c]);
            p0[c] = f0.x + f0.y;
            p1[c] = f1.x + f1.y;
        }
#pragma unroll
        for (int o = 16; o; o >>= 1)
#pragma unroll
            for (int c = 0; c < WAY; c++) {
                p0[c] += __shfl_xor_sync(0xFFFFFFFFu, p0[c], o);
                p1[c] += __shfl_xor_sync(0xFFFFFFFFu, p1[c], o);
            }

        if (lane == 0)
#pragma unroll
            for (int c = 0; c < WAY; c++) {
                red[warp][0][c] = p0[c];
                red[warp][1][c] = p1[c];
            }
        __syncthreads();
        if (tid < 2 * WAY) {
            int m = tid / WAY, c = tid % WAY;
            float s = 0.f;
#pragma unroll
            for (int w = 0; w < 8; w++) s += red[w][m][c];
            atomicAdd(&g_S2[c][q0 + m], s);
        }
        __syncthreads();   // buf1 free + red reusable
    }
}

// ---------------------------------------------------------------------------
// K6: logits (proven fast form)
// ---------------------------------------------------------------------------
__global__ void logits_kernel(float* __restrict__ out)
{
    int warp = (blockIdx.x * blockDim.x + threadIdx.x) >> 5;
    int lane = threadIdx.x & 31;
    if (warp >= NQ) return;
    const int q = warp;

    float s1[WAY] = {0.f, 0.f, 0.f, 0.f, 0.f};
    const float* qb = g_bar[NS + q];
    for (int k = lane; k < DD; k += 32) {
        float qv = qb[k];
#pragma unroll
        for (int c = 0; c < WAY; c++) s1[c] += g_sbarsum[c][k] * qv;
    }
#pragma unroll
    for (int o = 16; o; o >>= 1)
#pragma unroll
        for (int c = 0; c < WAY; c++)
            s1[c] += __shfl_xor_sync(0xFFFFFFFFu, s1[c], o);

    if (lane < WAY) {
        int c = lane;
        float cnt = (float)g_cls_cnt[c];
        out[q * WAY + c] = -2.f * (float)(FF * FF) + (4.f * s1[c] - 2.f * g_S2[c][q]) / cnt;
    }
}

// ---------------------------------------------------------------------------
extern "C" void kernel_launch(void* const* d_in, const int* in_sizes, int n_in,
                              void* d_out, int out_size)
{
    const float*     sg  = (const float*)d_in[0];
    const float*     sl  = (const float*)d_in[1];
    const long long* lab = (const long long*)d_in[2];
    const float*     qg  = (const float*)d_in[3];
    const float*     ql  = (const float*)d_in[4];
    float*           out = (float*)d_out;

    const int smem = 2 * 2 * SLICE * 2;   // 2 bufs x 2 slices = 87040 B
    static bool attr_set = false;
    if (!attr_set) {
        cudaFuncSetAttribute(sgram_kernel, cudaFuncAttributeMaxDynamicSharedMemorySize, smem);
        cudaFuncSetAttribute(qdot_kernel,  cudaFuncAttributeMaxDynamicSharedMemorySize, smem);
        attr_set = true;
    }

    norm_kernel<<<NITEM, 256>>>(sg, sl, qg, ql);          // normalize + rowsum
    prep_kernel<<<1, 512>>>(lab);
    sgram_kernel<<<NUNIT_S, 256, smem>>>();               // 250 units -> g_Gs
    classsum_kernel<<<dim3(KPACK / 1024, WAY), 256>>>();  // 800 CTAs -> g_Gp
    qdot_kernel<<<GGRID, 256, smem>>>();                  // 1000 paired units
    logits_kernel<<<(NQ * 32 + 255) / 256, 256>>>(out);
}

// round 17
// speedup vs baseline: 1.4533x; 1.0035x over previous
#include <cuda_runtime.h>
#include <cuda_fp16.h>
#include <cstdint>

#define NS     25
#define NQ     200
#define NITEM  (NS + NQ)        // 225
#define FF     80
#define DD     512
#define WAY    5
#define BLK    128
#define NBLK   10               // packed upper-tri 128x128 blocks of 4x4 grid
#define BLKSZ  (BLK * BLK)      // 16384 halves per block
#define KPACK  (NBLK * BLKSZ)   // 163840
#define PITCH  136              // smem pitch (halves) for X slices
#define SLICE  (FF * PITCH)     // halves per slice buffer
#define NUNIT_S (NBLK * NS)     // 250 support units
#define NPAIR   (NQ / 2)        // 100 query pairs
#define NUNIT_P (NBLK * NPAIR)  // 1000 paired query units
#define GGRID  296              // persistent CTAs (2/SM)

// -------- scratch (__device__ globals; no allocations allowed) --------------
__device__ __half g_Sn[NS * FF * DD];        // 2 MB   normalized supports
__device__ __half g_Qn[NQ * FF * DD];        // 16.4MB normalized queries
__device__ __half g_Gs[NS][KPACK];           // per-support Grams, frag order (x2 offdiag)
__device__ __half g_Gp[WAY][KPACK];          // class-summed Grams, frag order (1.6MB)
__device__ float  g_bar[NITEM][DD];          // per-item feature-row sums
__device__ float  g_sbarsum[WAY][DD];
__device__ int    g_cls_cnt[WAY];
__device__ int    g_cls_sup[WAY][NS];
__device__ float  g_S2[WAY][NQ];

__constant__ int c_bi[NBLK] = {0,0,0,0,1,1,1,2,2,3};
__constant__ int c_bj[NBLK] = {0,1,2,3,1,2,3,2,3,3};

// ---------------------------------------------------------------------------
// K1 (fused): per-item normalize + rowsum. One CTA per item. (proven)
// ---------------------------------------------------------------------------
__global__ void __launch_bounds__(256) norm_kernel(
    const float* __restrict__ sg, const float* __restrict__ sl,
    const float* __restrict__ qg, const float* __restrict__ ql)
{
    __shared__ float snorm[FF];
    const int item = blockIdx.x;
    const int tid  = threadIdx.x;
    const int lane = tid & 31;
    const int warp = tid >> 5;

    const float* gbase;
    const float* lbase;
    __half* dst;
    if (item < NS) {
        gbase = sg + (size_t)item * 16 * DD;
        lbase = sl + (size_t)item * 64 * DD;
        dst   = g_Sn + (size_t)item * FF * DD;
    } else {
        int q = item - NS;
        gbase = qg + (size_t)q * 16 * DD;
        lbase = ql + (size_t)q * 64 * DD;
        dst   = g_Qn + (size_t)q * FF * DD;
    }

    for (int f = warp; f < FF; f += 8) {
        const float4* src = (const float4*)((f < 16) ? gbase + (size_t)f * DD
                                                     : lbase + (size_t)(f - 16) * DD);
        float ss = 0.f;
#pragma unroll
        for (int i = 0; i < 4; i++) {
            float4 v = src[lane + 32 * i];
            ss += v.x * v.x + v.y * v.y + v.z * v.z + v.w * v.w;
        }
#pragma unroll
        for (int o = 16; o; o >>= 1) ss += __shfl_xor_sync(0xFFFFFFFFu, ss, o);
        if (lane == 0) snorm[f] = rsqrtf(fmaxf(ss, 1e-24f));
    }
    __syncthreads();

    float sx = 0.f, sy = 0.f;
#pragma unroll 4
    for (int f = 0; f < FF; f++) {
        const float2* src = (const float2*)((f < 16) ? gbase + (size_t)f * DD
                                                     : lbase + (size_t)(f - 16) * DD);
        float2 v = src[tid];
        float rn = snorm[f];
        float a = v.x * rn, b = v.y * rn;
        sx += a; sy += b;
        *(__half2*)(dst + (size_t)f * DD + 2 * tid) = __floats2half2_rn(a, b);
    }
    g_bar[item][2 * tid + 0] = sx;
    g_bar[item][2 * tid + 1] = sy;
}

// ---------------------------------------------------------------------------
// K2: class lists/counts, class-summed row-sums, zero S2 (proven)
// ---------------------------------------------------------------------------
__global__ void prep_kernel(const long long* __restrict__ labels)
{
    __shared__ int cnt[WAY];
    __shared__ int sup[WAY][NS];
    int t = threadIdx.x;  // 512
    if (t == 0) {
        for (int c = 0; c < WAY; c++) cnt[c] = 0;
        for (int s = 0; s < NS; s++) {
            int c = (int)labels[s];
            sup[c][cnt[c]++] = s;
        }
        for (int c = 0; c < WAY; c++) {
            g_cls_cnt[c] = cnt[c];
            for (int i = 0; i < cnt[c]; i++) g_cls_sup[c][i] = sup[c][i];
        }
    }
    __syncthreads();
    if (t < DD) {
#pragma unroll
        for (int c = 0; c < WAY; c++) {
            float a = 0.f;
            for (int i = 0; i < cnt[c]; i++) a += g_bar[sup[c][i]][t];
            g_sbarsum[c][t] = a;
        }
    }
    for (int i = t; i < WAY * NQ; i += blockDim.x)
        (&g_S2[0][0])[i] = 0.f;
}

// ---------------------------------------------------------------------------
// shared mma machinery — fp16 accumulators + software-pipelined fragments
// ---------------------------------------------------------------------------
__device__ __forceinline__ void ldsm_x4_t(uint32_t (&r)[4], const __half* p)
{
    uint32_t a = (uint32_t)__cvta_generic_to_shared(p);
    asm volatile("ldmatrix.sync.aligned.m8n8.x4.trans.shared.b16 {%0,%1,%2,%3}, [%4];"
                 : "=r"(r[0]), "=r"(r[1]), "=r"(r[2]), "=r"(r[3]) : "r"(a));
}

__device__ __forceinline__ void mma16816h(uint32_t (&d)[2], const uint32_t (&a)[4],
                                          uint32_t b0, uint32_t b1)
{
    asm volatile("mma.sync.aligned.m16n8k16.row.col.f16.f16.f16.f16 "
                 "{%0,%1},{%2,%3,%4,%5},{%6,%7},{%0,%1};"
                 : "+r"(d[0]), "+r"(d[1])
                 : "r"(a[0]), "r"(a[1]), "r"(a[2]), "r"(a[3]), "r"(b0), "r"(b1));
}

// Software-pipelined: prefetch k16+1 fragments while issuing k16's 16 HMMA.
__device__ __forceinline__ void gram_block_mma_h(
    const __half* sX0, const __half* pB, uint32_t (&acc)[2][8][2],
    int m_base, int n_base, int lane)
{
    const int a_krow = ((lane >> 4) << 3) + (lane & 7);
    const int a_coff = ((lane >> 3) & 1) << 3;
    const int b_krow = (((lane >> 3) & 1) << 3) + (lane & 7);
    const int b_coff = (lane >> 4) << 3;

    uint32_t a[2][2][4];    // [buf][mt][frag]
    uint32_t bf[2][4][4];   // [buf][nt][frag]

    // preload k16 = 0 into buf 0
#pragma unroll
    for (int mt = 0; mt < 2; mt++)
        ldsm_x4_t(a[0][mt], &sX0[a_krow * PITCH + m_base + mt * 16 + a_coff]);
#pragma unroll
    for (int nt = 0; nt < 4; nt++)
        ldsm_x4_t(bf[0][nt], &pB[b_krow * PITCH + n_base + nt * 16 + b_coff]);

#pragma unroll
    for (int k16 = 0; k16 < FF / 16; k16++) {
        const int cur = k16 & 1, nxt = cur ^ 1;
        if (k16 + 1 < FF / 16) {
            const int k1 = (k16 + 1) * 16;
#pragma unroll
            for (int mt = 0; mt < 2; mt++)
                ldsm_x4_t(a[nxt][mt], &sX0[(k1 + a_krow) * PITCH + m_base + mt * 16 + a_coff]);
#pragma unroll
            for (int nt = 0; nt < 4; nt++)
                ldsm_x4_t(bf[nxt][nt], &pB[(k1 + b_krow) * PITCH + n_base + nt * 16 + b_coff]);
        }
#pragma unroll
        for (int nt = 0; nt < 4; nt++) {
#pragma unroll
            for (int mt = 0; mt < 2; mt++) {
                mma16816h(acc[mt][2 * nt + 0], a[cur][mt], bf[cur][nt][0], bf[cur][nt][1]);
                mma16816h(acc[mt][2 * nt + 1], a[cur][mt], bf[cur][nt][2], bf[cur][nt][3]);
            }
        }
    }
}

extern __shared__ char dynsmem[];

// stage in {0,1}: each stage holds 2 slices
__device__ __forceinline__ void issue_slice_load(
    const __half* base, int b, int stage, int tid)
{
    const int bi = c_bi[b], bj = c_bj[b];
    __half* s0 = (__half*)dynsmem + stage * 2 * SLICE;
    const int nch = (bi == bj) ? 1280 : 2560;
    for (int ch = tid; ch < nch; ch += 256) {
        int tile = (ch >= 1280) ? 1 : 0;
        int rem  = ch - tile * 1280;
        int r = rem >> 4, cc = rem & 15;
        int colblk = tile ? bj : bi;
        const __half* src = base + (size_t)r * DD + colblk * 128 + cc * 8;
        __half* dsts = s0 + tile * SLICE + r * PITCH + cc * 8;
        uint32_t dst = (uint32_t)__cvta_generic_to_shared(dsts);
        asm volatile("cp.async.cg.shared.global [%0], [%1], 16;" :: "r"(dst), "l"(src));
    }
    asm volatile("cp.async.commit_group;");
}

// ---------------------------------------------------------------------------
// K3: support Gram (persistent, fp16 acc, proven). 250 units -> g_Gs.
// ---------------------------------------------------------------------------
__global__ void __launch_bounds__(256, 2) sgram_kernel()
{
    const int tid  = threadIdx.x;
    const int lane = tid & 31;
    const int warp = tid >> 5;
    const int m_base = (warp >> 1) * 32;
    const int n_base = (warp & 1) * 64;

    int u = blockIdx.x;
    if (u >= NUNIT_S) return;

    issue_slice_load(g_Sn + (size_t)(u / NBLK) * FF * DD, u % NBLK, 0, tid);
    int stage = 0;

    for (; u < NUNIT_S; u += gridDim.x) {
        const int nextu = u + gridDim.x;
        if (nextu < NUNIT_S) {
            issue_slice_load(g_Sn + (size_t)(nextu / NBLK) * FF * DD, nextu % NBLK,
                             stage ^ 1, tid);
            asm volatile("cp.async.wait_group 1;");
        } else {
            asm volatile("cp.async.wait_group 0;");
        }
        __syncthreads();

        const int item = u / NBLK, b = u % NBLK;
        const bool diag = (c_bi[b] == c_bj[b]);
        const __half* s0 = (const __half*)dynsmem + stage * 2 * SLICE;
        const __half* pB = diag ? s0 : s0 + SLICE;

        uint32_t acc[2][8][2];
#pragma unroll
        for (int mt = 0; mt < 2; mt++)
#pragma unroll
            for (int nt = 0; nt < 8; nt++)
                acc[mt][nt][0] = acc[mt][nt][1] = 0u;

        gram_block_mma_h(s0, pB, acc, m_base, n_base, lane);

        const __half2 two2 = __floats2half2_rn(2.f, 2.f);
        __half* out = g_Gs[item] + (size_t)b * BLKSZ;
#pragma unroll
        for (int j = 0; j < 8; j++) {
            const int mt = j >> 2, nt0 = (j & 3) * 2;
            uint32_t h[4] = {acc[mt][nt0][0], acc[mt][nt0][1],
                             acc[mt][nt0 + 1][0], acc[mt][nt0 + 1][1]};
            if (!diag) {
#pragma unroll
                for (int k = 0; k < 4; k++) {
                    __half2 v = __hmul2(*(__half2*)&h[k], two2);
                    h[k] = *(uint32_t*)&v;
                }
            }
            *(int4*)(out + (size_t)(j * 256 + tid) * 8) = *(int4*)h;
        }
        __syncthreads();
        stage ^= 1;
    }
}

// ---------------------------------------------------------------------------
// K4: classsum v5 EXACT (proven 7.2us): per-class CTAs, uint2 width,
// grid (160, 5) = 800 CTAs.
// ---------------------------------------------------------------------------
__global__ void __launch_bounds__(256) classsum_kernel()
{
    const int c    = blockIdx.y;
    const int base = blockIdx.x * 1024 + threadIdx.x * 4;   // 4 halves/thread
    const int cnt  = g_cls_cnt[c];

    float a0 = 0.f, a1 = 0.f, a2 = 0.f, a3 = 0.f;
#pragma unroll 5
    for (int i = 0; i < cnt; i++) {
        uint2 v = *(const uint2*)&g_Gs[g_cls_sup[c][i]][base];
        float2 p0 = __half22float2(*(const __half2*)&v.x);
        float2 p1 = __half22float2(*(const __half2*)&v.y);
        a0 += p0.x; a1 += p0.y; a2 += p1.x; a3 += p1.y;
    }
    uint2 o;
    *(__half2*)&o.x = __floats2half2_rn(a0, a1);
    *(__half2*)&o.y = __floats2half2_rn(a2, a3);
    *(uint2*)&g_Gp[c][base] = o;
}

// ---------------------------------------------------------------------------
// K5: qdot-pair (proven R16 structure) with pipelined mma.
// ---------------------------------------------------------------------------
__global__ void __launch_bounds__(256, 2) qdot_kernel()
{
    __shared__ float red[8][2][WAY];

    const int tid  = threadIdx.x;
    const int lane = tid & 31;
    const int warp = tid >> 5;
    const int m_base = (warp >> 1) * 32;
    const int n_base = (warp & 1) * 64;

    int u = blockIdx.x;
    if (u >= NUNIT_P) return;

    {
        const int b = u % NBLK, pair = u / NBLK;
        issue_slice_load(g_Qn + (size_t)(2 * pair) * FF * DD, b, 0, tid);
    }

    for (; u < NUNIT_P; u += gridDim.x) {
        const int b = u % NBLK, pair = u / NBLK;
        const bool diag = (c_bi[b] == c_bj[b]);
        const int q0 = 2 * pair;

        issue_slice_load(g_Qn + (size_t)(q0 + 1) * FF * DD, b, 1, tid);
        asm volatile("cp.async.wait_group 1;");
        __syncthreads();

        uint32_t acc0[2][8][2], acc1[2][8][2];
#pragma unroll
        for (int mt = 0; mt < 2; mt++)
#pragma unroll
            for (int nt = 0; nt < 8; nt++) {
                acc0[mt][nt][0] = acc0[mt][nt][1] = 0u;
                acc1[mt][nt][0] = acc1[mt][nt][1] = 0u;
            }

        {   // member 0 mma from buf0
            const __half* s0 = (const __half*)dynsmem;
            const __half* pB = diag ? s0 : s0 + SLICE;
            gram_block_mma_h(s0, pB, acc0, m_base, n_base, lane);
        }
        __syncthreads();   // buf0 free

        const int nu = u + gridDim.x;
        if (nu < NUNIT_P) {
            issue_slice_load(g_Qn + (size_t)(2 * (nu / NBLK)) * FF * DD,
                             nu % NBLK, 0, tid);
            asm volatile("cp.async.wait_group 1;");
        } else {
            asm volatile("cp.async.wait_group 0;");
        }
        __syncthreads();

        {   // member 1 mma from buf1
            const __half* s1 = (const __half*)dynsmem + 2 * SLICE;
            const __half* pB = diag ? s1 : s1 + SLICE;
            gram_block_mma_h(s1, pB, acc1, m_base, n_base, lane);
        }

        // ---- fused dot: ONE Gc pass serves both accumulator sets ----
        __half2 h0[WAY], h1[WAY];
#pragma unroll
        for (int c = 0; c < WAY; c++) {
            h0[c] = __floats2half2_rn(0.f, 0.f);
            h1[c] = __floats2half2_rn(0.f, 0.f);
        }
#pragma unroll
        for (int j = 0; j < 8; j++) {
            const int mt = j >> 2, nt0 = (j & 3) * 2;
            const size_t off = (size_t)b * BLKSZ + (size_t)(j * 256 + tid) * 8;
            const __half2 a00 = *(const __half2*)&acc0[mt][nt0][0];
            const __half2 a01 = *(const __half2*)&acc0[mt][nt0][1];
            const __half2 a02 = *(const __half2*)&acc0[mt][nt0 + 1][0];
            const __half2 a03 = *(const __half2*)&acc0[mt][nt0 + 1][1];
            const __half2 a10 = *(const __half2*)&acc1[mt][nt0][0];
            const __half2 a11 = *(const __half2*)&acc1[mt][nt0][1];
            const __half2 a12 = *(const __half2*)&acc1[mt][nt0 + 1][0];
            const __half2 a13 = *(const __half2*)&acc1[mt][nt0 + 1][1];
#pragma unroll
            for (int c = 0; c < WAY; c++) {
                int4 gv = *(const int4*)&g_Gp[c][off];
                const __half2* gh = (const __half2*)&gv;
                h0[c] = __hfma2(gh[0], a00, h0[c]);
                h1[c] = __hfma2(gh[0], a10, h1[c]);
                h0[c] = __hfma2(gh[1], a01, h0[c]);
                h1[c] = __hfma2(gh[1], a11, h1[c]);
                h0[c] = __hfma2(gh[2], a02, h0[c]);
                h1[c] = __hfma2(gh[2], a12, h1[c]);
                h0[c] = __hfma2(gh[3], a03, h0[c]);
                h1[c] = __hfma2(gh[3], a13, h1[c]);
            }
        }

        float p0[WAY], p1[WAY];
#pragma unroll
        for (int c = 0; c < WAY; c++) {
            float2 f0 = __half22float2(h0[c]);
            float2 f1 = __half22float2(h1[c]);
            p0[c] = f0.x + f0.y;
            p1[c] = f1.x + f1.y;
        }
#pragma unroll
        for (int o = 16; o; o >>= 1)
#pragma unroll
            for (int c = 0; c < WAY; c++) {
                p0[c] += __shfl_xor_sync(0xFFFFFFFFu, p0[c], o);
                p1[c] += __shfl_xor_sync(0xFFFFFFFFu, p1[c], o);
            }

        if (lane == 0)
#pragma unroll
            for (int c = 0; c < WAY; c++) {
                red[warp][0][c] = p0[c];
                red[warp][1][c] = p1[c];
            }
        __syncthreads();
        if (tid < 2 * WAY) {
            int m = tid / WAY, c = tid % WAY;
            float s = 0.f;
#pragma unroll
            for (int w = 0; w < 8; w++) s += red[w][m][c];
            atomicAdd(&g_S2[c][q0 + m], s);
        }
        __syncthreads();
    }
}

// ---------------------------------------------------------------------------
// K6: logits (proven fast form)
// ---------------------------------------------------------------------------
__global__ void logits_kernel(float* __restrict__ out)
{
    int warp = (blockIdx.x * blockDim.x + threadIdx.x) >> 5;
    int lane = threadIdx.x & 31;
    if (warp >= NQ) return;
    const int q = warp;

    float s1[WAY] = {0.f, 0.f, 0.f, 0.f, 0.f};
    const float* qb = g_bar[NS + q];
    for (int k = lane; k < DD; k += 32) {
        float qv = qb[k];
#pragma unroll
        for (int c = 0; c < WAY; c++) s1[c] += g_sbarsum[c][k] * qv;
    }
#pragma unroll
    for (int o = 16; o; o >>= 1)
#pragma unroll
        for (int c = 0; c < WAY; c++)
            s1[c] += __shfl_xor_sync(0xFFFFFFFFu, s1[c], o);

    if (lane < WAY) {
        int c = lane;
        float cnt = (float)g_cls_cnt[c];
        out[q * WAY + c] = -2.f * (float)(FF * FF) + (4.f * s1[c] - 2.f * g_S2[c][q]) / cnt;
    }
}

// ---------------------------------------------------------------------------
extern "C" void kernel_launch(void* const* d_in, const int* in_sizes, int n_in,
                              void* d_out, int out_size)
{
    const float*     sg  = (const float*)d_in[0];
    const float*     sl  = (const float*)d_in[1];
    const long long* lab = (const long long*)d_in[2];
    const float*     qg  = (const float*)d_in[3];
    const float*     ql  = (const float*)d_in[4];
    float*           out = (float*)d_out;

    const int smem = 2 * 2 * SLICE * 2;   // 2 bufs x 2 slices = 87040 B
    static bool attr_set = false;
    if (!attr_set) {
        cudaFuncSetAttribute(sgram_kernel, cudaFuncAttributeMaxDynamicSharedMemorySize, smem);
        cudaFuncSetAttribute(qdot_kernel,  cudaFuncAttributeMaxDynamicSharedMemorySize, smem);
        attr_set = true;
    }

    norm_kernel<<<NITEM, 256>>>(sg, sl, qg, ql);          // normalize + rowsum
    prep_kernel<<<1, 512>>>(lab);
    sgram_kernel<<<NUNIT_S, 256, smem>>>();               // 250 units -> g_Gs
    classsum_kernel<<<dim3(KPACK / 1024, WAY), 256>>>();  // 800 CTAs -> g_Gp
    qdot_kernel<<<GGRID, 256, smem>>>();                  // 1000 paired units
    logits_kernel<<<(NQ * 32 + 255) / 256, 256>>>(out);
}